// round 2
// baseline (speedup 1.0000x reference)
#include <cuda_runtime.h>
#include <cuda_bf16.h>
#include <math.h>

// Problem constants
#define TT 4096   // tokens = B*S
#define EE 64     // experts
#define KK 8      // top_k
#define HH 1024   // hidden
#define FF 512    // expert ffn
#define CC 1024   // capacity

// -------- scratch (__device__ globals; no allocation allowed) --------
__device__ int   g_expert_index[TT * KK];
__device__ float g_weights[TT * KK];
__device__ int   g_pair_pos[TT * KK];
__device__ int   g_row_token[EE * CC];
__device__ int   g_count[EE];
__device__ alignas(16) float g_hbuf[(size_t)EE * CC * FF];   // 128 MB
__device__ alignas(16) float g_obuf[(size_t)EE * CC * HH];   // 256 MB

// ====================================================================
// Kernel 1: router — logits, sigmoid, biased top-8 (sorted, tie->low idx),
// unbiased normalized weights.
// ====================================================================
__global__ void router_kernel(const float* __restrict__ x,
                              const float* __restrict__ w_router,
                              const float* __restrict__ bias,
                              float* __restrict__ logits_out,
                              float* __restrict__ idx_out)
{
    int t = blockIdx.x;
    __shared__ alignas(16) float sx[HH];
    __shared__ float slog[EE];
    __shared__ float saff[EE];
    __shared__ float ssel[EE];

    const float* xr = x + (size_t)t * HH;
    for (int i = threadIdx.x; i < HH; i += blockDim.x) sx[i] = xr[i];
    __syncthreads();

    int warp = threadIdx.x >> 5;
    int lane = threadIdx.x & 31;

    // 8 warps x 8 experts each
    for (int e = warp * 8; e < warp * 8 + 8; ++e) {
        const float* wr = w_router + (size_t)e * HH;
        float s = 0.f;
        for (int h = lane; h < HH; h += 32) s += sx[h] * wr[h];
        #pragma unroll
        for (int o = 16; o; o >>= 1) s += __shfl_xor_sync(0xffffffffu, s, o);
        if (lane == 0) {
            slog[e] = s;
            if (logits_out) logits_out[(size_t)t * EE + e] = s;
        }
    }
    __syncthreads();

    if (warp == 0) {
        // affinity + selection score
        for (int e = lane; e < EE; e += 32) {
            float l = slog[e];
            float a = 1.0f / (1.0f + expf(-l));
            saff[e] = a;
            ssel[e] = a + bias[e];
        }
        __syncwarp();

        int sel_idx[KK];
        #pragma unroll
        for (int k = 0; k < KK; ++k) {
            float v  = ssel[lane];      int id = lane;
            float v2 = ssel[lane + 32];
            if (v2 > v) { v = v2; id = lane + 32; }
            #pragma unroll
            for (int o = 16; o; o >>= 1) {
                float ov = __shfl_xor_sync(0xffffffffu, v, o);
                int   oi = __shfl_xor_sync(0xffffffffu, id, o);
                if (ov > v || (ov == v && oi < id)) { v = ov; id = oi; }
            }
            sel_idx[k] = id;
            if (lane == 0) ssel[id] = -INFINITY;
            __syncwarp();
        }

        if (lane == 0) {
            float wsum = 0.f;
            float wv[KK];
            #pragma unroll
            for (int k = 0; k < KK; ++k) { wv[k] = saff[sel_idx[k]]; wsum += wv[k]; }
            #pragma unroll
            for (int k = 0; k < KK; ++k) {
                g_expert_index[t * KK + k] = sel_idx[k];
                g_weights[t * KK + k]      = wv[k] / wsum;
                if (idx_out) idx_out[(size_t)t * KK + k] = (float)sel_idx[k];
            }
        }
    }
}

// ====================================================================
// Kernel 2: slot assignment — pos(i) = # prior pairs routed to same expert
// (exact order of flattened [t,k]). One block per expert.
// ====================================================================
__global__ void pos_kernel()
{
    int e   = blockIdx.x;
    int tid = threadIdx.x;
    const int NP    = TT * KK;      // 32768
    const int chunk = NP / 256;     // 128
    __shared__ int scnt[256];

    int base = tid * chunk;
    int c = 0;
    for (int j = 0; j < chunk; ++j)
        if (g_expert_index[base + j] == e) c++;
    scnt[tid] = c;
    __syncthreads();

    if (tid == 0) {
        int run = 0;
        for (int i = 0; i < 256; ++i) { int v = scnt[i]; scnt[i] = run; run += v; }
        g_count[e] = run;
    }
    __syncthreads();

    int off = scnt[tid];
    for (int j = 0; j < chunk; ++j) {
        int i = base + j;
        if (g_expert_index[i] == e) {
            g_pair_pos[i] = off;
            if (off < CC) g_row_token[e * CC + off] = i / KK;
            off++;
        }
    }
}

// ====================================================================
// Kernel 3: fused gate+up GEMM + SiLU*u -> hbuf.
// Tile 64x64, BK=32, 256 threads (16x16 micro-tile 4x4, two accum sets).
// A rows gathered via g_row_token (no [E,C,H] buffer materialized).
// grid = (F/64, C/64, E)
// ====================================================================
__global__ void __launch_bounds__(256) gemm1_kernel(const float* __restrict__ x,
                                                    const float* __restrict__ w_gate,
                                                    const float* __restrict__ w_up)
{
    const int e  = blockIdx.z;
    const int m0 = blockIdx.y * 64;
    const int n0 = blockIdx.x * 64;

    __shared__ int   scnt;
    __shared__ int   stok[64];
    __shared__ alignas(16) float As [32 * 64];
    __shared__ alignas(16) float Bgs[32 * 64];
    __shared__ alignas(16) float Bus[32 * 64];

    int tid = threadIdx.x;
    if (tid == 0) {
        int c = g_count[e];
        scnt = (c < CC) ? c : CC;
    }
    __syncthreads();
    const int cnt = scnt;
    if (m0 >= cnt) return;

    if (tid < 64) {
        int slot = m0 + tid;
        stok[tid] = (slot < cnt) ? g_row_token[e * CC + slot] : -1;
    }
    __syncthreads();

    const int tx = tid & 15;   // 0..15 -> n
    const int ty = tid >> 4;   // 0..15 -> m

    float accg[4][4]; float accu[4][4];
    #pragma unroll
    for (int i = 0; i < 4; ++i)
        #pragma unroll
        for (int j = 0; j < 4; ++j) { accg[i][j] = 0.f; accu[i][j] = 0.f; }

    // loaders
    const int ar  = tid >> 2;        // 0..63 row
    const int ac4 = tid & 3;         // base float4 col
    const int bk  = tid >> 3;        // 0..31 k-row
    const int bf  = tid & 7;         // base float4 col

    const float* wg_base = w_gate + (size_t)e * HH * FF + n0;
    const float* wu_base = w_up   + (size_t)e * HH * FF + n0;

    for (int k0 = 0; k0 < HH; k0 += 32) {
        // ---- load A (64 x 32), gathered rows ----
        {
            int tok = stok[ar];
            const float* xp = (tok >= 0) ? (x + (size_t)tok * HH + k0) : nullptr;
            #pragma unroll
            for (int p = 0; p < 2; ++p) {
                int c4 = ac4 + p * 4;                 // 0..7
                float4 v = make_float4(0.f, 0.f, 0.f, 0.f);
                if (xp) v = reinterpret_cast<const float4*>(xp)[c4];
                As[(c4 * 4 + 0) * 64 + ar] = v.x;
                As[(c4 * 4 + 1) * 64 + ar] = v.y;
                As[(c4 * 4 + 2) * 64 + ar] = v.z;
                As[(c4 * 4 + 3) * 64 + ar] = v.w;
            }
        }
        // ---- load Bg, Bu (32 x 64) ----
        {
            const float* gp = wg_base + (size_t)(k0 + bk) * FF;
            const float* up = wu_base + (size_t)(k0 + bk) * FF;
            #pragma unroll
            for (int p = 0; p < 2; ++p) {
                int f4 = bf + p * 8;                  // 0..15
                reinterpret_cast<float4*>(&Bgs[bk * 64])[f4] =
                    reinterpret_cast<const float4*>(gp)[f4];
                reinterpret_cast<float4*>(&Bus[bk * 64])[f4] =
                    reinterpret_cast<const float4*>(up)[f4];
            }
        }
        __syncthreads();

        #pragma unroll
        for (int kk = 0; kk < 32; ++kk) {
            float4 a  = reinterpret_cast<const float4*>(&As [kk * 64])[ty];
            float4 bg = reinterpret_cast<const float4*>(&Bgs[kk * 64])[tx];
            float4 bu = reinterpret_cast<const float4*>(&Bus[kk * 64])[tx];
            float av[4] = {a.x, a.y, a.z, a.w};
            float gv[4] = {bg.x, bg.y, bg.z, bg.w};
            float uv[4] = {bu.x, bu.y, bu.z, bu.w};
            #pragma unroll
            for (int i = 0; i < 4; ++i)
                #pragma unroll
                for (int j = 0; j < 4; ++j) {
                    accg[i][j] += av[i] * gv[j];
                    accu[i][j] += av[i] * uv[j];
                }
        }
        __syncthreads();
    }

    // epilogue: h = silu(g) * u
    #pragma unroll
    for (int i = 0; i < 4; ++i) {
        int m = m0 + ty * 4 + i;
        if (m < cnt) {
            float4 hv;
            float* hvp = reinterpret_cast<float*>(&hv);
            #pragma unroll
            for (int j = 0; j < 4; ++j) {
                float g = accg[i][j];
                float s = g / (1.0f + expf(-g));   // silu
                hvp[j] = s * accu[i][j];
            }
            reinterpret_cast<float4*>(
                &g_hbuf[((size_t)e * CC + m) * FF + n0 + tx * 4])[0] = hv;
        }
    }
}

// ====================================================================
// Kernel 4: down GEMM: hbuf[rows,F] x w_down[e][F][H] -> obuf[rows,H]
// grid = (H/64, C/64, E)
// ====================================================================
__global__ void __launch_bounds__(256) gemm2_kernel(const float* __restrict__ w_down)
{
    const int e  = blockIdx.z;
    const int m0 = blockIdx.y * 64;
    const int n0 = blockIdx.x * 64;

    __shared__ int   scnt;
    __shared__ alignas(16) float As[32 * 64];
    __shared__ alignas(16) float Bs[32 * 64];

    int tid = threadIdx.x;
    if (tid == 0) {
        int c = g_count[e];
        scnt = (c < CC) ? c : CC;
    }
    __syncthreads();
    const int cnt = scnt;
    if (m0 >= cnt) return;

    const int tx = tid & 15;
    const int ty = tid >> 4;

    float acc[4][4];
    #pragma unroll
    for (int i = 0; i < 4; ++i)
        #pragma unroll
        for (int j = 0; j < 4; ++j) acc[i][j] = 0.f;

    const int ar  = tid >> 2;
    const int ac4 = tid & 3;
    const int bk  = tid >> 3;
    const int bf  = tid & 7;

    const float* hrow_base = &g_hbuf[((size_t)e * CC + m0) * FF];
    const float* wd_base   = w_down + (size_t)e * FF * HH + n0;

    for (int k0 = 0; k0 < FF; k0 += 32) {
        {
            bool ok = (m0 + ar) < cnt;
            const float* ap = hrow_base + (size_t)ar * FF + k0;
            #pragma unroll
            for (int p = 0; p < 2; ++p) {
                int c4 = ac4 + p * 4;
                float4 v = make_float4(0.f, 0.f, 0.f, 0.f);
                if (ok) v = reinterpret_cast<const float4*>(ap)[c4];
                As[(c4 * 4 + 0) * 64 + ar] = v.x;
                As[(c4 * 4 + 1) * 64 + ar] = v.y;
                As[(c4 * 4 + 2) * 64 + ar] = v.z;
                As[(c4 * 4 + 3) * 64 + ar] = v.w;
            }
        }
        {
            const float* bp = wd_base + (size_t)(k0 + bk) * HH;
            #pragma unroll
            for (int p = 0; p < 2; ++p) {
                int f4 = bf + p * 8;
                reinterpret_cast<float4*>(&Bs[bk * 64])[f4] =
                    reinterpret_cast<const float4*>(bp)[f4];
            }
        }
        __syncthreads();

        #pragma unroll
        for (int kk = 0; kk < 32; ++kk) {
            float4 a = reinterpret_cast<const float4*>(&As[kk * 64])[ty];
            float4 b = reinterpret_cast<const float4*>(&Bs[kk * 64])[tx];
            float av[4] = {a.x, a.y, a.z, a.w};
            float bv[4] = {b.x, b.y, b.z, b.w};
            #pragma unroll
            for (int i = 0; i < 4; ++i)
                #pragma unroll
                for (int j = 0; j < 4; ++j)
                    acc[i][j] += av[i] * bv[j];
        }
        __syncthreads();
    }

    #pragma unroll
    for (int i = 0; i < 4; ++i) {
        int m = m0 + ty * 4 + i;
        if (m < cnt) {
            float4 ov = make_float4(acc[i][0], acc[i][1], acc[i][2], acc[i][3]);
            reinterpret_cast<float4*>(
                &g_obuf[((size_t)e * CC + m) * HH + n0 + tx * 4])[0] = ov;
        }
    }
}

// ====================================================================
// Kernel 5: combine — y[t] = sum_k w[t,k] * obuf[row(t,k)]
// ====================================================================
__global__ void combine_kernel(float* __restrict__ y)
{
    int t = blockIdx.x;
    __shared__ int   srow[KK];
    __shared__ float sw[KK];
    if (threadIdx.x < KK) {
        int i = t * KK + threadIdx.x;
        int e = g_expert_index[i];
        int p = g_pair_pos[i];
        srow[threadIdx.x] = (p < CC) ? (e * CC + p) : -1;
        sw[threadIdx.x]   = g_weights[i];
    }
    __syncthreads();

    for (int h = threadIdx.x; h < HH; h += blockDim.x) {
        float acc = 0.f;
        #pragma unroll
        for (int k = 0; k < KK; ++k) {
            int r = srow[k];
            if (r >= 0) acc += sw[k] * g_obuf[(size_t)r * HH + h];
        }
        y[(size_t)t * HH + h] = acc;
    }
}

// ====================================================================
extern "C" void kernel_launch(void* const* d_in, const int* in_sizes, int n_in,
                              void* d_out, int out_size)
{
    const float* x        = (const float*)d_in[0];
    const float* w_router = (const float*)d_in[1];
    const float* bias     = (const float*)d_in[2];
    const float* w_gate   = (const float*)d_in[3];
    const float* w_up     = (const float*)d_in[4];
    const float* w_down   = (const float*)d_in[5];

    float* y = (float*)d_out;
    float* logits_out = nullptr;
    float* idx_out    = nullptr;
    long long base = (long long)TT * HH;                       // 4194304
    if ((long long)out_size >= base + (long long)TT * EE)
        logits_out = y + base;
    if ((long long)out_size >= base + (long long)TT * EE + (long long)TT * KK)
        idx_out = y + base + (long long)TT * EE;

    router_kernel<<<TT, 256>>>(x, w_router, bias, logits_out, idx_out);
    pos_kernel<<<EE, 256>>>();
    gemm1_kernel<<<dim3(FF / 64, CC / 64, EE), 256>>>(x, w_gate, w_up);
    gemm2_kernel<<<dim3(HH / 64, CC / 64, EE), 256>>>(w_down);
    combine_kernel<<<TT, 256>>>(y);
}

// round 4
// speedup vs baseline: 1.2179x; 1.2179x over previous
#include <cuda_runtime.h>
#include <cuda_bf16.h>
#include <math.h>
#include <stdint.h>

// Problem constants
#define TT 4096   // tokens = B*S
#define EE 64     // experts
#define KK 8      // top_k
#define HH 1024   // hidden
#define FF 512    // expert ffn
#define CC 1024   // capacity

// -------- scratch (__device__ globals; no allocation allowed) --------
__device__ int   g_expert_index[TT * KK];
__device__ float g_weights[TT * KK];
__device__ int   g_pair_pos[TT * KK];
__device__ int   g_row_token[EE * CC];
__device__ int   g_count[EE];
__device__ alignas(16) float g_hbuf[(size_t)EE * CC * FF];   // 134 MB
__device__ alignas(16) float g_obuf[(size_t)EE * CC * HH];   // 268 MB

// -------- helpers --------
__device__ __forceinline__ float to_tf32(float f) {
    float r;
    asm("cvt.rna.tf32.f32 %0, %1;" : "=f"(r) : "f"(f));
    return r;
}

__device__ __forceinline__ void mma_tf32(float* c, const uint32_t* a, const uint32_t* b) {
    asm volatile(
        "mma.sync.aligned.m16n8k8.row.col.f32.tf32.tf32.f32 "
        "{%0,%1,%2,%3},{%4,%5,%6,%7},{%8,%9},{%0,%1,%2,%3};"
        : "+f"(c[0]), "+f"(c[1]), "+f"(c[2]), "+f"(c[3])
        : "r"(a[0]), "r"(a[1]), "r"(a[2]), "r"(a[3]), "r"(b[0]), "r"(b[1]));
}

// ====================================================================
// Kernel 1: router — exact fp32 (must match reference top-k bitwise)
// ====================================================================
__global__ void router_kernel(const float* __restrict__ x,
                              const float* __restrict__ w_router,
                              const float* __restrict__ bias,
                              float* __restrict__ logits_out,
                              float* __restrict__ idx_out)
{
    int t = blockIdx.x;
    __shared__ alignas(16) float sx[HH];
    __shared__ float slog[EE];
    __shared__ float saff[EE];
    __shared__ float ssel[EE];

    const float* xr = x + (size_t)t * HH;
    for (int i = threadIdx.x; i < HH; i += blockDim.x) sx[i] = xr[i];
    __syncthreads();

    int warp = threadIdx.x >> 5;
    int lane = threadIdx.x & 31;

    for (int e = warp * 8; e < warp * 8 + 8; ++e) {
        const float* wr = w_router + (size_t)e * HH;
        float s = 0.f;
        for (int h = lane; h < HH; h += 32) s += sx[h] * wr[h];
        #pragma unroll
        for (int o = 16; o; o >>= 1) s += __shfl_xor_sync(0xffffffffu, s, o);
        if (lane == 0) {
            slog[e] = s;
            if (logits_out) logits_out[(size_t)t * EE + e] = s;
        }
    }
    __syncthreads();

    if (warp == 0) {
        for (int e = lane; e < EE; e += 32) {
            float l = slog[e];
            float a = 1.0f / (1.0f + expf(-l));
            saff[e] = a;
            ssel[e] = a + bias[e];
        }
        __syncwarp();

        int sel_idx[KK];
        #pragma unroll
        for (int k = 0; k < KK; ++k) {
            float v  = ssel[lane];      int id = lane;
            float v2 = ssel[lane + 32];
            if (v2 > v) { v = v2; id = lane + 32; }
            #pragma unroll
            for (int o = 16; o; o >>= 1) {
                float ov = __shfl_xor_sync(0xffffffffu, v, o);
                int   oi = __shfl_xor_sync(0xffffffffu, id, o);
                if (ov > v || (ov == v && oi < id)) { v = ov; id = oi; }
            }
            sel_idx[k] = id;
            if (lane == 0) ssel[id] = -INFINITY;
            __syncwarp();
        }

        if (lane == 0) {
            float wsum = 0.f;
            float wv[KK];
            #pragma unroll
            for (int k = 0; k < KK; ++k) { wv[k] = saff[sel_idx[k]]; wsum += wv[k]; }
            #pragma unroll
            for (int k = 0; k < KK; ++k) {
                g_expert_index[t * KK + k] = sel_idx[k];
                g_weights[t * KK + k]      = wv[k] / wsum;
                if (idx_out) idx_out[(size_t)t * KK + k] = (float)sel_idx[k];
            }
        }
    }
}

// ====================================================================
// Kernel 2: slot assignment (exact order of flattened [t,k])
// ====================================================================
__global__ void pos_kernel()
{
    int e   = blockIdx.x;
    int tid = threadIdx.x;
    const int NP    = TT * KK;
    const int chunk = NP / 256;
    __shared__ int scnt[256];

    int base = tid * chunk;
    int c = 0;
    for (int j = 0; j < chunk; ++j)
        if (g_expert_index[base + j] == e) c++;
    scnt[tid] = c;
    __syncthreads();

    if (tid == 0) {
        int run = 0;
        for (int i = 0; i < 256; ++i) { int v = scnt[i]; scnt[i] = run; run += v; }
        g_count[e] = run;
    }
    __syncthreads();

    int off = scnt[tid];
    for (int j = 0; j < chunk; ++j) {
        int i = base + j;
        if (g_expert_index[i] == e) {
            g_pair_pos[i] = off;
            if (off < CC) g_row_token[e * CC + off] = i / KK;
            off++;
        }
    }
}

// ====================================================================
// Kernel 3: gate+up GEMM + SiLU*u -> hbuf  (mma.sync tf32)
// CTA tile: M=128 (capacity rows), N=64 (F cols), both gate & up.
// BK=32.  8 warps as 4(m) x 2(n); warp tile 32m x 32n per output.
// SMEM in fragment-major layout:
//   As_f[ks][mf][lane][4]  (4 ksteps, 8 mfrags)  -> LDS.128 reads
//   B*_f[ks][nf][lane][2]  (4 ksteps, 8 nfrags)  -> LDS.64 reads
// grid = (CC/128=8 [m, fastest], FF/64=8 [n], EE)
// ====================================================================
__global__ void __launch_bounds__(256) gemm1_mma(const float* __restrict__ x,
                                                 const float* __restrict__ w_gate,
                                                 const float* __restrict__ w_up)
{
    const int e  = blockIdx.z;
    const int m0 = blockIdx.x * 128;
    const int n0 = blockIdx.y * 64;

    int cnt = g_count[e];
    cnt = (cnt < CC) ? cnt : CC;
    if (m0 >= cnt) return;

    __shared__ alignas(16) float As_f[4 * 8 * 32 * 4];   // 16KB
    __shared__ alignas(16) float Bg_f[4 * 8 * 32 * 2];   // 8KB
    __shared__ alignas(16) float Bu_f[4 * 8 * 32 * 2];   // 8KB
    __shared__ int stok[128];

    const int tid  = threadIdx.x;
    const int wid  = tid >> 5;
    const int lane = tid & 31;
    const int wm   = wid >> 1;      // 0..3
    const int wn   = wid & 1;       // 0..1

    if (tid < 128) {
        int slot = m0 + tid;
        if (slot >= cnt) slot = cnt - 1;
        stok[tid] = g_row_token[e * CC + slot];
    }
    __syncthreads();

    float accg[2][4][4];
    float accu[2][4][4];
    #pragma unroll
    for (int mi = 0; mi < 2; ++mi)
        #pragma unroll
        for (int nj = 0; nj < 4; ++nj)
            #pragma unroll
            for (int q = 0; q < 4; ++q) { accg[mi][nj][q] = 0.f; accu[mi][nj][q] = 0.f; }

    // loader indices (A): 1024 float4 per chunk -> 4 per thread
    const int a_row = tid >> 3;         // base pattern uses linear; computed in loop
    (void)a_row;

    const float* wg_base = w_gate + (size_t)e * HH * FF + n0;
    const float* wu_base = w_up   + (size_t)e * HH * FF + n0;

    const uint32_t* As_u = reinterpret_cast<const uint32_t*>(As_f);
    const uint32_t* Bg_u = reinterpret_cast<const uint32_t*>(Bg_f);
    const uint32_t* Bu_u = reinterpret_cast<const uint32_t*>(Bu_f);

    for (int kc = 0; kc < HH / 32; ++kc) {
        const int k0 = kc * 32;

        // ---- load A (128 x 32) gathered rows -> fragment-major ----
        #pragma unroll
        for (int p = 0; p < 4; ++p) {
            int linear = p * 256 + tid;
            int row = linear >> 3;        // 0..127
            int c4  = linear & 7;         // 0..7 float4 within 32 cols
            float4 v = *reinterpret_cast<const float4*>(
                x + (size_t)stok[row] * HH + k0 + c4 * 4);
            int mf   = row >> 4;
            int frow = row & 15;
            int rr   = (frow >> 3) + ((c4 & 1) << 1);
            int ks   = c4 >> 1;
            float* dst = &As_f[(((ks << 3) + mf) << 7) + ((frow & 7) << 4) + rr];
            dst[0]  = to_tf32(v.x);
            dst[4]  = to_tf32(v.y);
            dst[8]  = to_tf32(v.z);
            dst[12] = to_tf32(v.w);
        }
        // ---- load Bg, Bu (32 x 64) -> fragment-major ----
        #pragma unroll
        for (int p = 0; p < 2; ++p) {
            int linear = p * 256 + tid;
            int krow = linear >> 4;       // 0..31
            int n4   = linear & 15;       // float4 col
            float4 vg = *reinterpret_cast<const float4*>(
                wg_base + (size_t)(k0 + krow) * FF + n4 * 4);
            float4 vu = *reinterpret_cast<const float4*>(
                wu_base + (size_t)(k0 + krow) * FF + n4 * 4);
            int ks = krow >> 3;
            int kk = krow & 7;
            int rb = kk >> 2;
            int nf = n4 >> 1;
            int base = ((((ks << 3) + nf) << 5) + ((n4 & 1) << 4) + (kk & 3)) * 2 + rb;
            Bg_f[base + 0]  = to_tf32(vg.x);
            Bg_f[base + 8]  = to_tf32(vg.y);
            Bg_f[base + 16] = to_tf32(vg.z);
            Bg_f[base + 24] = to_tf32(vg.w);
            Bu_f[base + 0]  = to_tf32(vu.x);
            Bu_f[base + 8]  = to_tf32(vu.y);
            Bu_f[base + 16] = to_tf32(vu.z);
            Bu_f[base + 24] = to_tf32(vu.w);
        }
        __syncthreads();

        #pragma unroll
        for (int ks = 0; ks < 4; ++ks) {
            uint32_t a[2][4];
            #pragma unroll
            for (int mi = 0; mi < 2; ++mi) {
                uint4 av = *reinterpret_cast<const uint4*>(
                    &As_u[(((ks << 3) + wm * 2 + mi) << 7) + (lane << 2)]);
                a[mi][0] = av.x; a[mi][1] = av.y; a[mi][2] = av.z; a[mi][3] = av.w;
            }
            #pragma unroll
            for (int nj = 0; nj < 4; ++nj) {
                int nf = wn * 4 + nj;
                uint2 bg = *reinterpret_cast<const uint2*>(
                    &Bg_u[((((ks << 3) + nf) << 5) + lane) * 2]);
                uint2 bu = *reinterpret_cast<const uint2*>(
                    &Bu_u[((((ks << 3) + nf) << 5) + lane) * 2]);
                uint32_t bgr[2] = {bg.x, bg.y};
                uint32_t bur[2] = {bu.x, bu.y};
                #pragma unroll
                for (int mi = 0; mi < 2; ++mi) {
                    mma_tf32(accg[mi][nj], a[mi], bgr);
                    mma_tf32(accu[mi][nj], a[mi], bur);
                }
            }
        }
        __syncthreads();
    }

    // ---- epilogue: h = silu(g) * u ----
    const int frow = lane >> 2;
    const int fcol = (lane & 3) * 2;
    #pragma unroll
    for (int mi = 0; mi < 2; ++mi) {
        #pragma unroll
        for (int nj = 0; nj < 4; ++nj) {
            int m = m0 + wm * 32 + mi * 16 + frow;
            int n = n0 + wn * 32 + nj * 8 + fcol;
            #pragma unroll
            for (int half = 0; half < 2; ++half) {
                float g0 = accg[mi][nj][half * 2 + 0];
                float g1 = accg[mi][nj][half * 2 + 1];
                float u0 = accu[mi][nj][half * 2 + 0];
                float u1 = accu[mi][nj][half * 2 + 1];
                float2 hv;
                hv.x = (g0 / (1.0f + expf(-g0))) * u0;
                hv.y = (g1 / (1.0f + expf(-g1))) * u1;
                *reinterpret_cast<float2*>(
                    &g_hbuf[((size_t)e * CC + m + half * 8) * FF + n]) = hv;
            }
        }
    }
}

// ====================================================================
// Kernel 4: down GEMM: hbuf x w_down -> obuf  (mma.sync tf32)
// CTA tile: M=128, N=128 (H cols).  BK=32, K=512.
// 8 warps 4(m) x 2(n); warp tile 32m x 64n (8 n-frags).
//   As_f[ks][mf][lane][4]   (16KB)
//   Bd_f[ks][nf16][lane][2] (16KB)
// grid = (CC/128=8 [m, fastest], HH/128=8 [n], EE)
// ====================================================================
__global__ void __launch_bounds__(256) gemm2_mma(const float* __restrict__ w_down)
{
    const int e  = blockIdx.z;
    const int m0 = blockIdx.x * 128;
    const int n0 = blockIdx.y * 128;

    int cnt = g_count[e];
    cnt = (cnt < CC) ? cnt : CC;
    if (m0 >= cnt) return;

    __shared__ alignas(16) float As_f[4 * 8 * 32 * 4];    // 16KB
    __shared__ alignas(16) float Bd_f[4 * 16 * 32 * 2];   // 16KB

    const int tid  = threadIdx.x;
    const int wid  = tid >> 5;
    const int lane = tid & 31;
    const int wm   = wid >> 1;      // 0..3
    const int wn   = wid & 1;       // 0..1

    float acc[2][8][4];
    #pragma unroll
    for (int mi = 0; mi < 2; ++mi)
        #pragma unroll
        for (int nj = 0; nj < 8; ++nj)
            #pragma unroll
            for (int q = 0; q < 4; ++q) acc[mi][nj][q] = 0.f;

    const float* a_base = g_hbuf + ((size_t)e * CC + m0) * FF;
    const float* b_base = w_down + (size_t)e * FF * HH + n0;

    const uint32_t* As_u = reinterpret_cast<const uint32_t*>(As_f);
    const uint32_t* Bd_u = reinterpret_cast<const uint32_t*>(Bd_f);

    for (int kc = 0; kc < FF / 32; ++kc) {
        const int k0 = kc * 32;

        // ---- A (128 x 32) from hbuf ----
        #pragma unroll
        for (int p = 0; p < 4; ++p) {
            int linear = p * 256 + tid;
            int row = linear >> 3;
            int c4  = linear & 7;
            float4 v = *reinterpret_cast<const float4*>(
                a_base + (size_t)row * FF + k0 + c4 * 4);
            int mf   = row >> 4;
            int frow = row & 15;
            int rr   = (frow >> 3) + ((c4 & 1) << 1);
            int ks   = c4 >> 1;
            float* dst = &As_f[(((ks << 3) + mf) << 7) + ((frow & 7) << 4) + rr];
            dst[0]  = to_tf32(v.x);
            dst[4]  = to_tf32(v.y);
            dst[8]  = to_tf32(v.z);
            dst[12] = to_tf32(v.w);
        }
        // ---- B (32 x 128) from w_down ----
        #pragma unroll
        for (int p = 0; p < 4; ++p) {
            int linear = p * 256 + tid;
            int krow = linear >> 5;       // 0..31
            int n4   = linear & 31;       // float4 col of 128
            float4 v = *reinterpret_cast<const float4*>(
                b_base + (size_t)(k0 + krow) * HH + n4 * 4);
            int ks = krow >> 3;
            int kk = krow & 7;
            int rb = kk >> 2;
            int nf = n4 >> 1;             // 0..15
            int base = ((((ks << 4) + nf) << 5) + ((n4 & 1) << 4) + (kk & 3)) * 2 + rb;
            Bd_f[base + 0]  = to_tf32(v.x);
            Bd_f[base + 8]  = to_tf32(v.y);
            Bd_f[base + 16] = to_tf32(v.z);
            Bd_f[base + 24] = to_tf32(v.w);
        }
        __syncthreads();

        #pragma unroll
        for (int ks = 0; ks < 4; ++ks) {
            uint32_t a[2][4];
            #pragma unroll
            for (int mi = 0; mi < 2; ++mi) {
                uint4 av = *reinterpret_cast<const uint4*>(
                    &As_u[(((ks << 3) + wm * 2 + mi) << 7) + (lane << 2)]);
                a[mi][0] = av.x; a[mi][1] = av.y; a[mi][2] = av.z; a[mi][3] = av.w;
            }
            #pragma unroll
            for (int nj = 0; nj < 8; ++nj) {
                int nf = wn * 8 + nj;
                uint2 bd = *reinterpret_cast<const uint2*>(
                    &Bd_u[((((ks << 4) + nf) << 5) + lane) * 2]);
                uint32_t br[2] = {bd.x, bd.y};
                #pragma unroll
                for (int mi = 0; mi < 2; ++mi)
                    mma_tf32(acc[mi][nj], a[mi], br);
            }
        }
        __syncthreads();
    }

    const int frow = lane >> 2;
    const int fcol = (lane & 3) * 2;
    #pragma unroll
    for (int mi = 0; mi < 2; ++mi) {
        #pragma unroll
        for (int nj = 0; nj < 8; ++nj) {
            int m = m0 + wm * 32 + mi * 16 + frow;
            int n = n0 + wn * 64 + nj * 8 + fcol;
            #pragma unroll
            for (int half = 0; half < 2; ++half) {
                float2 ov;
                ov.x = acc[mi][nj][half * 2 + 0];
                ov.y = acc[mi][nj][half * 2 + 1];
                *reinterpret_cast<float2*>(
                    &g_obuf[((size_t)e * CC + m + half * 8) * HH + n]) = ov;
            }
        }
    }
}

// ====================================================================
// Kernel 5: combine — y[t] = sum_k w[t,k] * obuf[row(t,k)]
// ====================================================================
__global__ void combine_kernel(float* __restrict__ y)
{
    int t = blockIdx.x;
    __shared__ int   srow[KK];
    __shared__ float sw[KK];
    if (threadIdx.x < KK) {
        int i = t * KK + threadIdx.x;
        int e = g_expert_index[i];
        int p = g_pair_pos[i];
        srow[threadIdx.x] = (p < CC) ? (e * CC + p) : -1;
        sw[threadIdx.x]   = g_weights[i];
    }
    __syncthreads();

    for (int h = threadIdx.x; h < HH; h += blockDim.x) {
        float acc = 0.f;
        #pragma unroll
        for (int k = 0; k < KK; ++k) {
            int r = srow[k];
            if (r >= 0) acc += sw[k] * g_obuf[(size_t)r * HH + h];
        }
        y[(size_t)t * HH + h] = acc;
    }
}

// ====================================================================
extern "C" void kernel_launch(void* const* d_in, const int* in_sizes, int n_in,
                              void* d_out, int out_size)
{
    const float* x        = (const float*)d_in[0];
    const float* w_router = (const float*)d_in[1];
    const float* bias     = (const float*)d_in[2];
    const float* w_gate   = (const float*)d_in[3];
    const float* w_up     = (const float*)d_in[4];
    const float* w_down   = (const float*)d_in[5];

    float* y = (float*)d_out;
    float* logits_out = nullptr;
    float* idx_out    = nullptr;
    long long base = (long long)TT * HH;
    if ((long long)out_size >= base + (long long)TT * EE)
        logits_out = y + base;
    if ((long long)out_size >= base + (long long)TT * EE + (long long)TT * KK)
        idx_out = y + base + (long long)TT * EE;

    router_kernel<<<TT, 256>>>(x, w_router, bias, logits_out, idx_out);
    pos_kernel<<<EE, 256>>>();
    gemm1_mma<<<dim3(CC / 128, FF / 64, EE), 256>>>(x, w_gate, w_up);
    gemm2_mma<<<dim3(CC / 128, HH / 128, EE), 256>>>(w_down);
    combine_kernel<<<TT, 256>>>(y);
}

// round 6
// speedup vs baseline: 2.0881x; 1.7144x over previous
#include <cuda_runtime.h>
#include <cuda_bf16.h>
#include <math.h>
#include <stdint.h>

// Problem constants
#define TT 4096   // tokens = B*S
#define EE 64     // experts
#define KK 8      // top_k
#define HH 1024   // hidden
#define FF 512    // expert ffn
#define CC 1024   // capacity

// -------- scratch (__device__ globals; no allocation allowed) --------
__device__ int   g_expert_index[TT * KK];
__device__ float g_weights[TT * KK];
__device__ int   g_pair_pos[TT * KK];
__device__ int   g_row_token[EE * CC];
__device__ int   g_count[EE];
__device__ alignas(16) float g_hbuf[(size_t)EE * CC * FF];   // 134 MB
__device__ alignas(16) float g_obuf[(size_t)EE * CC * HH];   // 268 MB

// -------- helpers --------
__device__ __forceinline__ float to_tf32(float f) {
    float r;
    asm("cvt.rna.tf32.f32 %0, %1;" : "=f"(r) : "f"(f));
    return r;
}
__device__ __forceinline__ float4 cvt4(float4 v) {
    return make_float4(to_tf32(v.x), to_tf32(v.y), to_tf32(v.z), to_tf32(v.w));
}
__device__ __forceinline__ void mma_tf32(float* c, const uint32_t* a, const uint32_t* b) {
    asm volatile(
        "mma.sync.aligned.m16n8k8.row.col.f32.tf32.tf32.f32 "
        "{%0,%1,%2,%3},{%4,%5,%6,%7},{%8,%9},{%0,%1,%2,%3};"
        : "+f"(c[0]), "+f"(c[1]), "+f"(c[2]), "+f"(c[3])
        : "r"(a[0]), "r"(a[1]), "r"(a[2]), "r"(a[3]), "r"(b[0]), "r"(b[1]));
}
__device__ __forceinline__ uint32_t ldsf(const float* p) {
    return __float_as_uint(*p);
}

// ====================================================================
// Kernel 1: router — exact fp32 (must match reference top-k bitwise)
// ====================================================================
__global__ void router_kernel(const float* __restrict__ x,
                              const float* __restrict__ w_router,
                              const float* __restrict__ bias,
                              float* __restrict__ logits_out,
                              float* __restrict__ idx_out)
{
    int t = blockIdx.x;
    __shared__ alignas(16) float sx[HH];
    __shared__ float slog[EE];
    __shared__ float saff[EE];
    __shared__ float ssel[EE];

    const float* xr = x + (size_t)t * HH;
    for (int i = threadIdx.x; i < HH; i += blockDim.x) sx[i] = xr[i];
    __syncthreads();

    int warp = threadIdx.x >> 5;
    int lane = threadIdx.x & 31;

    for (int e = warp * 8; e < warp * 8 + 8; ++e) {
        const float* wr = w_router + (size_t)e * HH;
        float s = 0.f;
        for (int h = lane; h < HH; h += 32) s += sx[h] * wr[h];
        #pragma unroll
        for (int o = 16; o; o >>= 1) s += __shfl_xor_sync(0xffffffffu, s, o);
        if (lane == 0) {
            slog[e] = s;
            if (logits_out) logits_out[(size_t)t * EE + e] = s;
        }
    }
    __syncthreads();

    if (warp == 0) {
        for (int e = lane; e < EE; e += 32) {
            float l = slog[e];
            float a = 1.0f / (1.0f + expf(-l));
            saff[e] = a;
            ssel[e] = a + bias[e];
        }
        __syncwarp();

        int sel_idx[KK];
        #pragma unroll
        for (int k = 0; k < KK; ++k) {
            float v  = ssel[lane];      int id = lane;
            float v2 = ssel[lane + 32];
            if (v2 > v) { v = v2; id = lane + 32; }
            #pragma unroll
            for (int o = 16; o; o >>= 1) {
                float ov = __shfl_xor_sync(0xffffffffu, v, o);
                int   oi = __shfl_xor_sync(0xffffffffu, id, o);
                if (ov > v || (ov == v && oi < id)) { v = ov; id = oi; }
            }
            sel_idx[k] = id;
            if (lane == 0) ssel[id] = -INFINITY;
            __syncwarp();
        }

        if (lane == 0) {
            float wsum = 0.f;
            float wv[KK];
            #pragma unroll
            for (int k = 0; k < KK; ++k) { wv[k] = saff[sel_idx[k]]; wsum += wv[k]; }
            #pragma unroll
            for (int k = 0; k < KK; ++k) {
                g_expert_index[t * KK + k] = sel_idx[k];
                g_weights[t * KK + k]      = wv[k] / wsum;
                if (idx_out) idx_out[(size_t)t * KK + k] = (float)sel_idx[k];
            }
        }
    }
}

// ====================================================================
// Kernel 2: slot assignment (exact order of flattened [t,k])
// ====================================================================
__global__ void pos_kernel()
{
    int e   = blockIdx.x;
    int tid = threadIdx.x;
    const int NP    = TT * KK;
    const int chunk = NP / 256;
    __shared__ int scnt[256];

    int base = tid * chunk;
    int c = 0;
    for (int j = 0; j < chunk; ++j)
        if (g_expert_index[base + j] == e) c++;
    scnt[tid] = c;
    __syncthreads();

    if (tid == 0) {
        int run = 0;
        for (int i = 0; i < 256; ++i) { int v = scnt[i]; scnt[i] = run; run += v; }
        g_count[e] = run;
    }
    __syncthreads();

    int off = scnt[tid];
    for (int j = 0; j < chunk; ++j) {
        int i = base + j;
        if (g_expert_index[i] == e) {
            g_pair_pos[i] = off;
            if (off < CC) g_row_token[e * CC + off] = i / KK;
            off++;
        }
    }
}

// ====================================================================
// Kernel 3: gate+up GEMM + SiLU*u -> hbuf  (mma.sync tf32)
// CTA: M=128, N=64, gate+up fused.  BK=32, double-buffered, swizzled.
// 8 warps 4(m) x 2(n); warp tile 32m x 32n per output.
// A tile: [128][32] floats, float4 idx = row*8 + (c4 ^ (row&7))
// B tiles: [32][64] floats, float4 idx = k*16 + (n4 ^ ((k&3)*2))
// grid = (CC/128=8 [m fastest], FF/64=8, EE)
// ====================================================================
__global__ void __launch_bounds__(256, 2) gemm1_mma(const float* __restrict__ x,
                                                    const float* __restrict__ w_gate,
                                                    const float* __restrict__ w_up)
{
    const int e  = blockIdx.z;
    const int m0 = blockIdx.x * 128;
    const int n0 = blockIdx.y * 64;

    int cnt = g_count[e];
    cnt = (cnt < CC) ? cnt : CC;
    if (m0 >= cnt) return;

    extern __shared__ float smem[];
    // float offsets: A0=0, A1=4096, Bg0=8192, Bg1=10240, Bu0=12288, Bu1=14336
    float* Abuf[2]  = { smem,          smem + 4096 };
    float* Bgbuf[2] = { smem + 8192,   smem + 10240 };
    float* Bubuf[2] = { smem + 12288,  smem + 14336 };

    __shared__ int stok[128];

    const int tid  = threadIdx.x;
    const int wid  = tid >> 5;
    const int lane = tid & 31;
    const int wm   = wid >> 1;      // 0..3
    const int wn   = wid & 1;       // 0..1

    if (tid < 128) {
        int slot = m0 + tid;
        if (slot >= cnt) slot = cnt - 1;
        stok[tid] = g_row_token[e * CC + slot];
    }
    __syncthreads();

    // ---- loader constants ----
    const int a_row  = tid >> 3;                 // 0..31 (+p*32)
    const int a_c4   = tid & 7;
    const int a_sw4  = a_c4 ^ (a_row & 7);       // swizzled float4 col
    const int b_krow = tid >> 4;                 // 0..15 (+p*16)
    const int b_n4   = tid & 15;
    const int b_sw4  = b_n4 ^ ((b_krow & 3) * 2);

    const float* wg_base = w_gate + (size_t)e * HH * FF + n0;
    const float* wu_base = w_up   + (size_t)e * HH * FF + n0;

    // fragment read constants
    const int q  = lane >> 2;
    const int cL = lane & 3;
    const int xB = cL << 3;

    float accg[2][4][4];
    float accu[2][4][4];
    #pragma unroll
    for (int mi = 0; mi < 2; ++mi)
        #pragma unroll
        for (int nj = 0; nj < 4; ++nj)
            #pragma unroll
            for (int qq = 0; qq < 4; ++qq) { accg[mi][nj][qq] = 0.f; accu[mi][nj][qq] = 0.f; }

    float4 a_pre[4], bg_pre[2], bu_pre[2];

    // prologue: global loads for chunk 0
    {
        const int k0 = 0;
        #pragma unroll
        for (int p = 0; p < 4; ++p)
            a_pre[p] = *reinterpret_cast<const float4*>(
                x + (size_t)stok[a_row + p * 32] * HH + k0 + a_c4 * 4);
        #pragma unroll
        for (int p = 0; p < 2; ++p) {
            size_t boff = (size_t)(k0 + b_krow + p * 16) * FF + b_n4 * 4;
            bg_pre[p] = *reinterpret_cast<const float4*>(wg_base + boff);
            bu_pre[p] = *reinterpret_cast<const float4*>(wu_base + boff);
        }
    }
    // store chunk 0
    {
        float4* A4  = reinterpret_cast<float4*>(Abuf[0]);
        float4* Bg4 = reinterpret_cast<float4*>(Bgbuf[0]);
        float4* Bu4 = reinterpret_cast<float4*>(Bubuf[0]);
        #pragma unroll
        for (int p = 0; p < 4; ++p)
            A4[p * 256 + (tid >> 3) * 8 + a_sw4] = cvt4(a_pre[p]);
        #pragma unroll
        for (int p = 0; p < 2; ++p) {
            Bg4[p * 256 + (tid >> 4) * 16 + b_sw4] = cvt4(bg_pre[p]);
            Bu4[p * 256 + (tid >> 4) * 16 + b_sw4] = cvt4(bu_pre[p]);
        }
    }
    __syncthreads();

    const int NK = HH / 32;   // 32
    for (int kc = 0; kc < NK; ++kc) {
        const int cur = kc & 1;
        // prefetch next chunk into regs
        if (kc + 1 < NK) {
            const int k0 = (kc + 1) * 32;
            #pragma unroll
            for (int p = 0; p < 4; ++p)
                a_pre[p] = *reinterpret_cast<const float4*>(
                    x + (size_t)stok[a_row + p * 32] * HH + k0 + a_c4 * 4);
            #pragma unroll
            for (int p = 0; p < 2; ++p) {
                size_t boff = (size_t)(k0 + b_krow + p * 16) * FF + b_n4 * 4;
                bg_pre[p] = *reinterpret_cast<const float4*>(wg_base + boff);
                bu_pre[p] = *reinterpret_cast<const float4*>(wu_base + boff);
            }
        }

        // compute current chunk
        const float* Ab  = Abuf[cur];
        const float* Bgb = Bgbuf[cur];
        const float* Bub = Bubuf[cur];
        #pragma unroll
        for (int ks = 0; ks < 4; ++ks) {
            uint32_t a[2][4];
            const int swc = (ks * 8 + cL) ^ (q << 2);
            #pragma unroll
            for (int mi = 0; mi < 2; ++mi) {
                const int rb = (wm * 32 + mi * 16 + q) * 32;
                a[mi][0] = ldsf(Ab + rb + swc);
                a[mi][1] = ldsf(Ab + rb + 256 + swc);
                a[mi][2] = ldsf(Ab + rb + (swc ^ 4));
                a[mi][3] = ldsf(Ab + rb + 256 + (swc ^ 4));
            }
            const int krow = (ks * 8 + cL) * 64;
            #pragma unroll
            for (int nj = 0; nj < 4; ++nj) {
                const int nsw = ((wn * 32 + nj * 8) ^ xB) + q;
                uint32_t bg[2], bu[2];
                bg[0] = ldsf(Bgb + krow + nsw);
                bg[1] = ldsf(Bgb + krow + 256 + nsw);
                bu[0] = ldsf(Bub + krow + nsw);
                bu[1] = ldsf(Bub + krow + 256 + nsw);
                #pragma unroll
                for (int mi = 0; mi < 2; ++mi) {
                    mma_tf32(accg[mi][nj], a[mi], bg);
                    mma_tf32(accu[mi][nj], a[mi], bu);
                }
            }
        }

        // store next chunk
        if (kc + 1 < NK) {
            const int nxt = cur ^ 1;
            float4* A4  = reinterpret_cast<float4*>(Abuf[nxt]);
            float4* Bg4 = reinterpret_cast<float4*>(Bgbuf[nxt]);
            float4* Bu4 = reinterpret_cast<float4*>(Bubuf[nxt]);
            #pragma unroll
            for (int p = 0; p < 4; ++p)
                A4[p * 256 + (tid >> 3) * 8 + a_sw4] = cvt4(a_pre[p]);
            #pragma unroll
            for (int p = 0; p < 2; ++p) {
                Bg4[p * 256 + (tid >> 4) * 16 + b_sw4] = cvt4(bg_pre[p]);
                Bu4[p * 256 + (tid >> 4) * 16 + b_sw4] = cvt4(bu_pre[p]);
            }
        }
        __syncthreads();
    }

    // ---- epilogue: h = silu(g) * u ----
    const int frow = lane >> 2;
    const int fcol = (lane & 3) * 2;
    #pragma unroll
    for (int mi = 0; mi < 2; ++mi) {
        #pragma unroll
        for (int nj = 0; nj < 4; ++nj) {
            int m = m0 + wm * 32 + mi * 16 + frow;
            int n = n0 + wn * 32 + nj * 8 + fcol;
            #pragma unroll
            for (int half = 0; half < 2; ++half) {
                float g0 = accg[mi][nj][half * 2 + 0];
                float g1 = accg[mi][nj][half * 2 + 1];
                float u0 = accu[mi][nj][half * 2 + 0];
                float u1 = accu[mi][nj][half * 2 + 1];
                float2 hv;
                hv.x = (g0 / (1.0f + expf(-g0))) * u0;
                hv.y = (g1 / (1.0f + expf(-g1))) * u1;
                *reinterpret_cast<float2*>(
                    &g_hbuf[((size_t)e * CC + m + half * 8) * FF + n]) = hv;
            }
        }
    }
}

// ====================================================================
// Kernel 4: down GEMM: hbuf x w_down -> obuf  (mma.sync tf32)
// CTA: M=128, N=128.  BK=32, double-buffered, swizzled.
// 8 warps 4(m) x 2(n); warp tile 32m x 64n.
// A tile: [128][32], float4 idx = row*8 + (c4 ^ (row&7))
// B tile: [32][128], float4 idx = k*32 + (n4 ^ ((k&3)*2))
// grid = (CC/128=8 [m fastest], HH/128=8, EE)
// ====================================================================
__global__ void __launch_bounds__(256, 2) gemm2_mma(const float* __restrict__ w_down)
{
    const int e  = blockIdx.z;
    const int m0 = blockIdx.x * 128;
    const int n0 = blockIdx.y * 128;

    int cnt = g_count[e];
    cnt = (cnt < CC) ? cnt : CC;
    if (m0 >= cnt) return;

    extern __shared__ float smem[];
    // float offsets: A0=0, A1=4096, B0=8192, B1=12288
    float* Abuf[2] = { smem,        smem + 4096 };
    float* Bbuf[2] = { smem + 8192, smem + 12288 };

    const int tid  = threadIdx.x;
    const int wid  = tid >> 5;
    const int lane = tid & 31;
    const int wm   = wid >> 1;
    const int wn   = wid & 1;

    const int a_row  = tid >> 3;
    const int a_c4   = tid & 7;
    const int a_sw4  = a_c4 ^ (a_row & 7);
    const int b_krow = tid >> 5;                 // 0..7 (+p*8)
    const int b_n4   = tid & 31;
    const int b_sw4  = b_n4 ^ ((b_krow & 3) * 2);

    const float* a_base = g_hbuf + ((size_t)e * CC + m0) * FF;
    const float* b_base = w_down + (size_t)e * FF * HH + n0;

    const int q  = lane >> 2;
    const int cL = lane & 3;
    const int xB = cL << 3;

    float acc[2][8][4];
    #pragma unroll
    for (int mi = 0; mi < 2; ++mi)
        #pragma unroll
        for (int nj = 0; nj < 8; ++nj)
            #pragma unroll
            for (int qq = 0; qq < 4; ++qq) acc[mi][nj][qq] = 0.f;

    float4 a_pre[4], b_pre[4];

    {
        const int k0 = 0;
        #pragma unroll
        for (int p = 0; p < 4; ++p)
            a_pre[p] = *reinterpret_cast<const float4*>(
                a_base + (size_t)(a_row + p * 32) * FF + k0 + a_c4 * 4);
        #pragma unroll
        for (int p = 0; p < 4; ++p)
            b_pre[p] = *reinterpret_cast<const float4*>(
                b_base + (size_t)(k0 + b_krow + p * 8) * HH + b_n4 * 4);
    }
    {
        float4* A4 = reinterpret_cast<float4*>(Abuf[0]);
        float4* B4 = reinterpret_cast<float4*>(Bbuf[0]);
        #pragma unroll
        for (int p = 0; p < 4; ++p)
            A4[p * 256 + (tid >> 3) * 8 + a_sw4] = cvt4(a_pre[p]);
        #pragma unroll
        for (int p = 0; p < 4; ++p)
            B4[p * 256 + (tid >> 5) * 32 + b_sw4] = cvt4(b_pre[p]);
    }
    __syncthreads();

    const int NK = FF / 32;   // 16
    for (int kc = 0; kc < NK; ++kc) {
        const int cur = kc & 1;
        if (kc + 1 < NK) {
            const int k0 = (kc + 1) * 32;
            #pragma unroll
            for (int p = 0; p < 4; ++p)
                a_pre[p] = *reinterpret_cast<const float4*>(
                    a_base + (size_t)(a_row + p * 32) * FF + k0 + a_c4 * 4);
            #pragma unroll
            for (int p = 0; p < 4; ++p)
                b_pre[p] = *reinterpret_cast<const float4*>(
                    b_base + (size_t)(k0 + b_krow + p * 8) * HH + b_n4 * 4);
        }

        const float* Ab = Abuf[cur];
        const float* Bb = Bbuf[cur];
        #pragma unroll
        for (int ks = 0; ks < 4; ++ks) {
            uint32_t a[2][4];
            const int swc = (ks * 8 + cL) ^ (q << 2);
            #pragma unroll
            for (int mi = 0; mi < 2; ++mi) {
                const int rb = (wm * 32 + mi * 16 + q) * 32;
                a[mi][0] = ldsf(Ab + rb + swc);
                a[mi][1] = ldsf(Ab + rb + 256 + swc);
                a[mi][2] = ldsf(Ab + rb + (swc ^ 4));
                a[mi][3] = ldsf(Ab + rb + 256 + (swc ^ 4));
            }
            const int krow = (ks * 8 + cL) * 128;
            #pragma unroll
            for (int nj = 0; nj < 8; ++nj) {
                const int nsw = ((wn * 64 + nj * 8) ^ xB) + q;
                uint32_t b[2];
                b[0] = ldsf(Bb + krow + nsw);
                b[1] = ldsf(Bb + krow + 512 + nsw);
                #pragma unroll
                for (int mi = 0; mi < 2; ++mi)
                    mma_tf32(acc[mi][nj], a[mi], b);
            }
        }

        if (kc + 1 < NK) {
            const int nxt = cur ^ 1;
            float4* A4 = reinterpret_cast<float4*>(Abuf[nxt]);
            float4* B4 = reinterpret_cast<float4*>(Bbuf[nxt]);
            #pragma unroll
            for (int p = 0; p < 4; ++p)
                A4[p * 256 + (tid >> 3) * 8 + a_sw4] = cvt4(a_pre[p]);
            #pragma unroll
            for (int p = 0; p < 4; ++p)
                B4[p * 256 + (tid >> 5) * 32 + b_sw4] = cvt4(b_pre[p]);
        }
        __syncthreads();
    }

    const int frow = lane >> 2;
    const int fcol = (lane & 3) * 2;
    #pragma unroll
    for (int mi = 0; mi < 2; ++mi) {
        #pragma unroll
        for (int nj = 0; nj < 8; ++nj) {
            int m = m0 + wm * 32 + mi * 16 + frow;
            int n = n0 + wn * 64 + nj * 8 + fcol;
            #pragma unroll
            for (int half = 0; half < 2; ++half) {
                float2 ov;
                ov.x = acc[mi][nj][half * 2 + 0];
                ov.y = acc[mi][nj][half * 2 + 1];
                *reinterpret_cast<float2*>(
                    &g_obuf[((size_t)e * CC + m + half * 8) * HH + n]) = ov;
            }
        }
    }
}

// ====================================================================
// Kernel 5: combine — y[t] = sum_k w[t,k] * obuf[row(t,k)]
// ====================================================================
__global__ void combine_kernel(float* __restrict__ y)
{
    int t = blockIdx.x;
    __shared__ int   srow[KK];
    __shared__ float sw[KK];
    if (threadIdx.x < KK) {
        int i = t * KK + threadIdx.x;
        int e = g_expert_index[i];
        int p = g_pair_pos[i];
        srow[threadIdx.x] = (p < CC) ? (e * CC + p) : -1;
        sw[threadIdx.x]   = g_weights[i];
    }
    __syncthreads();

    for (int h = threadIdx.x; h < HH; h += blockDim.x) {
        float acc = 0.f;
        #pragma unroll
        for (int k = 0; k < KK; ++k) {
            int r = srow[k];
            if (r >= 0) acc += sw[k] * g_obuf[(size_t)r * HH + h];
        }
        y[(size_t)t * HH + h] = acc;
    }
}

// ====================================================================
extern "C" void kernel_launch(void* const* d_in, const int* in_sizes, int n_in,
                              void* d_out, int out_size)
{
    const float* x        = (const float*)d_in[0];
    const float* w_router = (const float*)d_in[1];
    const float* bias     = (const float*)d_in[2];
    const float* w_gate   = (const float*)d_in[3];
    const float* w_up     = (const float*)d_in[4];
    const float* w_down   = (const float*)d_in[5];

    float* y = (float*)d_out;
    float* logits_out = nullptr;
    float* idx_out    = nullptr;
    long long base = (long long)TT * HH;
    if ((long long)out_size >= base + (long long)TT * EE)
        logits_out = y + base;
    if ((long long)out_size >= base + (long long)TT * EE + (long long)TT * KK)
        idx_out = y + base + (long long)TT * EE;

    const int SMEM1 = 65536;   // 16384 floats
    const int SMEM2 = 65536;
    cudaFuncSetAttribute(gemm1_mma, cudaFuncAttributeMaxDynamicSharedMemorySize, SMEM1);
    cudaFuncSetAttribute(gemm2_mma, cudaFuncAttributeMaxDynamicSharedMemorySize, SMEM2);

    router_kernel<<<TT, 256>>>(x, w_router, bias, logits_out, idx_out);
    pos_kernel<<<EE, 256>>>();
    gemm1_mma<<<dim3(CC / 128, FF / 64, EE), 256, SMEM1>>>(x, w_gate, w_up);
    gemm2_mma<<<dim3(CC / 128, HH / 128, EE), 256, SMEM2>>>(w_down);
    combine_kernel<<<TT, 256>>>(y);
}

// round 7
// speedup vs baseline: 4.5343x; 2.1715x over previous
#include <cuda_runtime.h>
#include <cuda_fp16.h>
#include <math.h>
#include <stdint.h>

// Problem constants
#define TT 4096   // tokens = B*S
#define EE 64     // experts
#define KK 8      // top_k
#define HH 1024   // hidden
#define FF 512    // expert ffn
#define CC 1024   // capacity

// -------- scratch (__device__ globals; no allocation allowed) --------
__device__ int   g_expert_index[TT * KK];
__device__ float g_weights[TT * KK];
__device__ int   g_pair_pos[TT * KK];
__device__ int   g_row_token[EE * CC];
__device__ int   g_count[EE];
__device__ alignas(16) __half g_hbuf[(size_t)EE * CC * FF];  // 67 MB (half)
__device__ alignas(16) float  g_obuf[(size_t)EE * CC * HH];  // 268 MB

// -------- helpers --------
__device__ __forceinline__ uint32_t smem_to_u32(const void* p) {
    uint32_t a;
    asm("{ .reg .u64 t; cvta.to.shared.u64 t, %1; cvt.u32.u64 %0, t; }"
        : "=r"(a) : "l"(p));
    return a;
}
__device__ __forceinline__ uint2 f4_to_h4(float4 v) {
    __half2 a = __floats2half2_rn(v.x, v.y);
    __half2 b = __floats2half2_rn(v.z, v.w);
    uint2 r;
    r.x = *reinterpret_cast<uint32_t*>(&a);
    r.y = *reinterpret_cast<uint32_t*>(&b);
    return r;
}
__device__ __forceinline__ void ldm_x4(uint32_t* r, uint32_t addr) {
    asm volatile("ldmatrix.sync.aligned.m8n8.x4.shared.b16 {%0,%1,%2,%3}, [%4];"
        : "=r"(r[0]), "=r"(r[1]), "=r"(r[2]), "=r"(r[3]) : "r"(addr));
}
__device__ __forceinline__ void ldm_x4t(uint32_t* r, uint32_t addr) {
    asm volatile("ldmatrix.sync.aligned.m8n8.x4.trans.shared.b16 {%0,%1,%2,%3}, [%4];"
        : "=r"(r[0]), "=r"(r[1]), "=r"(r[2]), "=r"(r[3]) : "r"(addr));
}
__device__ __forceinline__ void mma_f16(float* c, const uint32_t* a, const uint32_t* b) {
    asm volatile(
        "mma.sync.aligned.m16n8k16.row.col.f32.f16.f16.f32 "
        "{%0,%1,%2,%3},{%4,%5,%6,%7},{%8,%9},{%0,%1,%2,%3};"
        : "+f"(c[0]), "+f"(c[1]), "+f"(c[2]), "+f"(c[3])
        : "r"(a[0]), "r"(a[1]), "r"(a[2]), "r"(a[3]), "r"(b[0]), "r"(b[1]));
}

// ====================================================================
// Kernel 1: router — exact fp32 (must match reference top-k bitwise)
// ====================================================================
__global__ void router_kernel(const float* __restrict__ x,
                              const float* __restrict__ w_router,
                              const float* __restrict__ bias,
                              float* __restrict__ logits_out,
                              float* __restrict__ idx_out)
{
    int t = blockIdx.x;
    __shared__ alignas(16) float sx[HH];
    __shared__ float slog[EE];
    __shared__ float saff[EE];
    __shared__ float ssel[EE];

    const float* xr = x + (size_t)t * HH;
    for (int i = threadIdx.x; i < HH; i += blockDim.x) sx[i] = xr[i];
    __syncthreads();

    int warp = threadIdx.x >> 5;
    int lane = threadIdx.x & 31;

    for (int e = warp * 8; e < warp * 8 + 8; ++e) {
        const float* wr = w_router + (size_t)e * HH;
        float s = 0.f;
        for (int h = lane; h < HH; h += 32) s += sx[h] * wr[h];
        #pragma unroll
        for (int o = 16; o; o >>= 1) s += __shfl_xor_sync(0xffffffffu, s, o);
        if (lane == 0) {
            slog[e] = s;
            if (logits_out) logits_out[(size_t)t * EE + e] = s;
        }
    }
    __syncthreads();

    if (warp == 0) {
        for (int e = lane; e < EE; e += 32) {
            float l = slog[e];
            float a = 1.0f / (1.0f + expf(-l));
            saff[e] = a;
            ssel[e] = a + bias[e];
        }
        __syncwarp();

        int sel_idx[KK];
        #pragma unroll
        for (int k = 0; k < KK; ++k) {
            float v  = ssel[lane];      int id = lane;
            float v2 = ssel[lane + 32];
            if (v2 > v) { v = v2; id = lane + 32; }
            #pragma unroll
            for (int o = 16; o; o >>= 1) {
                float ov = __shfl_xor_sync(0xffffffffu, v, o);
                int   oi = __shfl_xor_sync(0xffffffffu, id, o);
                if (ov > v || (ov == v && oi < id)) { v = ov; id = oi; }
            }
            sel_idx[k] = id;
            if (lane == 0) ssel[id] = -INFINITY;
            __syncwarp();
        }

        if (lane == 0) {
            float wsum = 0.f;
            float wv[KK];
            #pragma unroll
            for (int k = 0; k < KK; ++k) { wv[k] = saff[sel_idx[k]]; wsum += wv[k]; }
            #pragma unroll
            for (int k = 0; k < KK; ++k) {
                g_expert_index[t * KK + k] = sel_idx[k];
                g_weights[t * KK + k]      = wv[k] / wsum;
                if (idx_out) idx_out[(size_t)t * KK + k] = (float)sel_idx[k];
            }
        }
    }
}

// ====================================================================
// Kernel 2: slot assignment (exact order of flattened [t,k])
// ====================================================================
__global__ void pos_kernel()
{
    int e   = blockIdx.x;
    int tid = threadIdx.x;
    const int NP    = TT * KK;
    const int chunk = NP / 256;
    __shared__ int scnt[256];

    int base = tid * chunk;
    int c = 0;
    for (int j = 0; j < chunk; ++j)
        if (g_expert_index[base + j] == e) c++;
    scnt[tid] = c;
    __syncthreads();

    if (tid == 0) {
        int run = 0;
        for (int i = 0; i < 256; ++i) { int v = scnt[i]; scnt[i] = run; run += v; }
        g_count[e] = run;
    }
    __syncthreads();

    int off = scnt[tid];
    for (int j = 0; j < chunk; ++j) {
        int i = base + j;
        if (g_expert_index[i] == e) {
            g_pair_pos[i] = off;
            if (off < CC) g_row_token[e * CC + off] = i / KK;
            off++;
        }
    }
}

// ====================================================================
// Kernel 3: gate+up GEMM + SiLU*u -> hbuf(half)  (mma.sync fp16 k16)
// CTA: M=128, N=64 (gate+up).  BK=32, double-buffered, row-padded tiles.
// 8 warps 4(m) x 2(n); warp tile 32m x 32n per output.
// A tile: [128 rows][32 halves], row stride 80B (conflict-free ldmatrix)
// B tiles: [32 k][64 n halves], row stride 144B
// grid = (CC/128=8 [m fastest], FF/64=8, EE)
// ====================================================================
__global__ void __launch_bounds__(256, 2) gemm1_mma(const float* __restrict__ x,
                                                    const float* __restrict__ w_gate,
                                                    const float* __restrict__ w_up)
{
    const int e  = blockIdx.z;
    const int m0 = blockIdx.x * 128;
    const int n0 = blockIdx.y * 64;

    int cnt = g_count[e];
    cnt = (cnt < CC) ? cnt : CC;
    if (m0 >= cnt) return;

    // byte offsets: A0=0(10240) A1=10240, Bg0=20480(4608) Bg1=25088,
    //               Bu0=29696 Bu1=34304; total 38912
    __shared__ alignas(16) unsigned char sbuf[38912];
    __shared__ int stok[128];

    const int tid  = threadIdx.x;
    const int wid  = tid >> 5;
    const int lane = tid & 31;
    const int wm   = wid >> 1;      // 0..3
    const int wn   = wid & 1;       // 0..1

    if (tid < 128) {
        int slot = m0 + tid;
        if (slot >= cnt) slot = cnt - 1;
        stok[tid] = g_row_token[e * CC + slot];
    }
    __syncthreads();

    const uint32_t sA = smem_to_u32(sbuf);

    // ---- loader constants ----
    const int a_row = tid >> 3;                 // 0..31 (+p*32)
    const int a_c4  = tid & 7;                  // float4 col (4 floats)
    const int b_krow = tid >> 4;                // 0..15 (+p*16)
    const int b_n4   = tid & 15;

    const float* wg_base = w_gate + (size_t)e * HH * FF + n0;
    const float* wu_base = w_up   + (size_t)e * HH * FF + n0;

    // ---- fragment address constants ----
    const int fa_row  = (lane & 7) + ((lane >> 3) & 1) * 8;   // + wm*32 + mi*16
    const int fa_koff = (lane >> 4) * 16;                     // bytes
    const int fb_k    = (lane & 7) + ((lane >> 3) & 1) * 8;   // + ks*16
    const int fb_noff = (wn * 32 + (lane >> 4) * 8) * 2;      // bytes; + pf*32

    float accg[2][4][4];
    float accu[2][4][4];
    #pragma unroll
    for (int mi = 0; mi < 2; ++mi)
        #pragma unroll
        for (int nj = 0; nj < 4; ++nj)
            #pragma unroll
            for (int qq = 0; qq < 4; ++qq) { accg[mi][nj][qq] = 0.f; accu[mi][nj][qq] = 0.f; }

    float4 a_pre[4], bg_pre[2], bu_pre[2];

    // prologue: global loads for chunk 0
    #pragma unroll
    for (int p = 0; p < 4; ++p)
        a_pre[p] = *reinterpret_cast<const float4*>(
            x + (size_t)stok[a_row + p * 32] * HH + a_c4 * 4);
    #pragma unroll
    for (int p = 0; p < 2; ++p) {
        size_t boff = (size_t)(b_krow + p * 16) * FF + b_n4 * 4;
        bg_pre[p] = *reinterpret_cast<const float4*>(wg_base + boff);
        bu_pre[p] = *reinterpret_cast<const float4*>(wu_base + boff);
    }
    // store chunk 0
    {
        #pragma unroll
        for (int p = 0; p < 4; ++p)
            *reinterpret_cast<uint2*>(sbuf + (a_row + p * 32) * 80 + a_c4 * 8) =
                f4_to_h4(a_pre[p]);
        #pragma unroll
        for (int p = 0; p < 2; ++p) {
            int off = (b_krow + p * 16) * 144 + b_n4 * 8;
            *reinterpret_cast<uint2*>(sbuf + 20480 + off) = f4_to_h4(bg_pre[p]);
            *reinterpret_cast<uint2*>(sbuf + 29696 + off) = f4_to_h4(bu_pre[p]);
        }
    }
    __syncthreads();

    const int NK = HH / 32;   // 32
    for (int kc = 0; kc < NK; ++kc) {
        const int cur = kc & 1;
        // prefetch next chunk into regs
        if (kc + 1 < NK) {
            const int k0 = (kc + 1) * 32;
            #pragma unroll
            for (int p = 0; p < 4; ++p)
                a_pre[p] = *reinterpret_cast<const float4*>(
                    x + (size_t)stok[a_row + p * 32] * HH + k0 + a_c4 * 4);
            #pragma unroll
            for (int p = 0; p < 2; ++p) {
                size_t boff = (size_t)(k0 + b_krow + p * 16) * FF + b_n4 * 4;
                bg_pre[p] = *reinterpret_cast<const float4*>(wg_base + boff);
                bu_pre[p] = *reinterpret_cast<const float4*>(wu_base + boff);
            }
        }

        // compute current chunk (2 ks of k16)
        const uint32_t Ab  = sA + cur * 10240;
        const uint32_t Bgb = sA + 20480 + cur * 4608;
        const uint32_t Bub = sA + 29696 + cur * 4608;
        #pragma unroll
        for (int ks = 0; ks < 2; ++ks) {
            uint32_t a[2][4];
            #pragma unroll
            for (int mi = 0; mi < 2; ++mi)
                ldm_x4(a[mi], Ab + (wm * 32 + mi * 16 + fa_row) * 80 + ks * 32 + fa_koff);
            #pragma unroll
            for (int pf = 0; pf < 2; ++pf) {
                uint32_t bg[4], bu[4];
                int boff = (ks * 16 + fb_k) * 144 + fb_noff + pf * 32;
                ldm_x4t(bg, Bgb + boff);
                ldm_x4t(bu, Bub + boff);
                #pragma unroll
                for (int mi = 0; mi < 2; ++mi) {
                    mma_f16(accg[mi][pf * 2 + 0], a[mi], bg + 0);
                    mma_f16(accg[mi][pf * 2 + 1], a[mi], bg + 2);
                    mma_f16(accu[mi][pf * 2 + 0], a[mi], bu + 0);
                    mma_f16(accu[mi][pf * 2 + 1], a[mi], bu + 2);
                }
            }
        }

        // store next chunk
        if (kc + 1 < NK) {
            unsigned char* nb = sbuf + (cur ^ 1) * 10240;
            #pragma unroll
            for (int p = 0; p < 4; ++p)
                *reinterpret_cast<uint2*>(nb + (a_row + p * 32) * 80 + a_c4 * 8) =
                    f4_to_h4(a_pre[p]);
            unsigned char* nbg = sbuf + 20480 + (cur ^ 1) * 4608;
            unsigned char* nbu = sbuf + 29696 + (cur ^ 1) * 4608;
            #pragma unroll
            for (int p = 0; p < 2; ++p) {
                int off = (b_krow + p * 16) * 144 + b_n4 * 8;
                *reinterpret_cast<uint2*>(nbg + off) = f4_to_h4(bg_pre[p]);
                *reinterpret_cast<uint2*>(nbu + off) = f4_to_h4(bu_pre[p]);
            }
        }
        __syncthreads();
    }

    // ---- epilogue: h = silu(g) * u -> half ----
    const int frow = lane >> 2;
    const int fcol = (lane & 3) * 2;
    #pragma unroll
    for (int mi = 0; mi < 2; ++mi) {
        #pragma unroll
        for (int nj = 0; nj < 4; ++nj) {
            int m = m0 + wm * 32 + mi * 16 + frow;
            int n = n0 + wn * 32 + nj * 8 + fcol;
            #pragma unroll
            for (int half = 0; half < 2; ++half) {
                float g0 = accg[mi][nj][half * 2 + 0];
                float g1 = accg[mi][nj][half * 2 + 1];
                float u0 = accu[mi][nj][half * 2 + 0];
                float u1 = accu[mi][nj][half * 2 + 1];
                float h0 = (g0 / (1.0f + expf(-g0))) * u0;
                float h1 = (g1 / (1.0f + expf(-g1))) * u1;
                *reinterpret_cast<__half2*>(
                    &g_hbuf[((size_t)e * CC + m + half * 8) * FF + n]) =
                    __floats2half2_rn(h0, h1);
            }
        }
    }
}

// ====================================================================
// Kernel 4: down GEMM: hbuf(half) x w_down -> obuf  (mma.sync fp16 k16)
// CTA: M=128, N=128.  BK=32, double-buffered, row-padded tiles.
// 8 warps 4(m) x 2(n); warp tile 32m x 64n.
// A tile: [128][32 halves], stride 80B.  B tile: [32 k][128 n], stride 272B.
// grid = (CC/128=8 [m fastest], HH/128=8, EE)
// ====================================================================
__global__ void __launch_bounds__(256, 2) gemm2_mma(const float* __restrict__ w_down)
{
    const int e  = blockIdx.z;
    const int m0 = blockIdx.x * 128;
    const int n0 = blockIdx.y * 128;

    int cnt = g_count[e];
    cnt = (cnt < CC) ? cnt : CC;
    if (m0 >= cnt) return;

    // byte offsets: A0=0(10240) A1=10240, B0=20480(8704) B1=29184; total 37888
    __shared__ alignas(16) unsigned char sbuf[37888];

    const int tid  = threadIdx.x;
    const int wid  = tid >> 5;
    const int lane = tid & 31;
    const int wm   = wid >> 1;
    const int wn   = wid & 1;

    // loaders: A from half hbuf (uint4 = 8 halves); B from fp32 w_down
    const int a_row = tid >> 2;                 // 0..63 (+p*64)
    const int a_q4  = tid & 3;                  // uint4 col (8 halves)
    const int b_krow = tid >> 5;                // 0..7 (+p*8)
    const int b_n4   = tid & 31;

    const __half* a_base = g_hbuf + ((size_t)e * CC + m0) * FF;
    const float*  b_base = w_down + (size_t)e * FF * HH + n0;

    const uint32_t sA = smem_to_u32(sbuf);

    const int fa_row  = (lane & 7) + ((lane >> 3) & 1) * 8;
    const int fa_koff = (lane >> 4) * 16;
    const int fb_k    = (lane & 7) + ((lane >> 3) & 1) * 8;
    const int fb_noff = (wn * 64 + (lane >> 4) * 8) * 2;

    float acc[2][8][4];
    #pragma unroll
    for (int mi = 0; mi < 2; ++mi)
        #pragma unroll
        for (int nj = 0; nj < 8; ++nj)
            #pragma unroll
            for (int qq = 0; qq < 4; ++qq) acc[mi][nj][qq] = 0.f;

    uint4  a_pre[2];
    float4 b_pre[4];

    // prologue chunk 0
    #pragma unroll
    for (int p = 0; p < 2; ++p)
        a_pre[p] = *reinterpret_cast<const uint4*>(
            a_base + (size_t)(a_row + p * 64) * FF + a_q4 * 8);
    #pragma unroll
    for (int p = 0; p < 4; ++p)
        b_pre[p] = *reinterpret_cast<const float4*>(
            b_base + (size_t)(b_krow + p * 8) * HH + b_n4 * 4);
    {
        #pragma unroll
        for (int p = 0; p < 2; ++p)
            *reinterpret_cast<uint4*>(sbuf + (a_row + p * 64) * 80 + a_q4 * 16) = a_pre[p];
        #pragma unroll
        for (int p = 0; p < 4; ++p)
            *reinterpret_cast<uint2*>(sbuf + 20480 + (b_krow + p * 8) * 272 + b_n4 * 8) =
                f4_to_h4(b_pre[p]);
    }
    __syncthreads();

    const int NK = FF / 32;   // 16
    for (int kc = 0; kc < NK; ++kc) {
        const int cur = kc & 1;
        if (kc + 1 < NK) {
            const int k0 = (kc + 1) * 32;
            #pragma unroll
            for (int p = 0; p < 2; ++p)
                a_pre[p] = *reinterpret_cast<const uint4*>(
                    a_base + (size_t)(a_row + p * 64) * FF + k0 + a_q4 * 8);
            #pragma unroll
            for (int p = 0; p < 4; ++p)
                b_pre[p] = *reinterpret_cast<const float4*>(
                    b_base + (size_t)(k0 + b_krow + p * 8) * HH + b_n4 * 4);
        }

        const uint32_t Ab = sA + cur * 10240;
        const uint32_t Bb = sA + 20480 + cur * 8704;
        #pragma unroll
        for (int ks = 0; ks < 2; ++ks) {
            uint32_t a[2][4];
            #pragma unroll
            for (int mi = 0; mi < 2; ++mi)
                ldm_x4(a[mi], Ab + (wm * 32 + mi * 16 + fa_row) * 80 + ks * 32 + fa_koff);
            #pragma unroll
            for (int pf = 0; pf < 4; ++pf) {
                uint32_t b[4];
                ldm_x4t(b, Bb + (ks * 16 + fb_k) * 272 + fb_noff + pf * 32);
                #pragma unroll
                for (int mi = 0; mi < 2; ++mi) {
                    mma_f16(acc[mi][pf * 2 + 0], a[mi], b + 0);
                    mma_f16(acc[mi][pf * 2 + 1], a[mi], b + 2);
                }
            }
        }

        if (kc + 1 < NK) {
            unsigned char* na = sbuf + (cur ^ 1) * 10240;
            unsigned char* nb = sbuf + 20480 + (cur ^ 1) * 8704;
            #pragma unroll
            for (int p = 0; p < 2; ++p)
                *reinterpret_cast<uint4*>(na + (a_row + p * 64) * 80 + a_q4 * 16) = a_pre[p];
            #pragma unroll
            for (int p = 0; p < 4; ++p)
                *reinterpret_cast<uint2*>(nb + (b_krow + p * 8) * 272 + b_n4 * 8) =
                    f4_to_h4(b_pre[p]);
        }
        __syncthreads();
    }

    const int frow = lane >> 2;
    const int fcol = (lane & 3) * 2;
    #pragma unroll
    for (int mi = 0; mi < 2; ++mi) {
        #pragma unroll
        for (int nj = 0; nj < 8; ++nj) {
            int m = m0 + wm * 32 + mi * 16 + frow;
            int n = n0 + wn * 64 + nj * 8 + fcol;
            #pragma unroll
            for (int half = 0; half < 2; ++half) {
                float2 ov;
                ov.x = acc[mi][nj][half * 2 + 0];
                ov.y = acc[mi][nj][half * 2 + 1];
                *reinterpret_cast<float2*>(
                    &g_obuf[((size_t)e * CC + m + half * 8) * HH + n]) = ov;
            }
        }
    }
}

// ====================================================================
// Kernel 5: combine — y[t] = sum_k w[t,k] * obuf[row(t,k)]
// ====================================================================
__global__ void combine_kernel(float* __restrict__ y)
{
    int t = blockIdx.x;
    __shared__ int   srow[KK];
    __shared__ float sw[KK];
    if (threadIdx.x < KK) {
        int i = t * KK + threadIdx.x;
        int e = g_expert_index[i];
        int p = g_pair_pos[i];
        srow[threadIdx.x] = (p < CC) ? (e * CC + p) : -1;
        sw[threadIdx.x]   = g_weights[i];
    }
    __syncthreads();

    for (int h = threadIdx.x; h < HH; h += blockDim.x) {
        float acc = 0.f;
        #pragma unroll
        for (int k = 0; k < KK; ++k) {
            int r = srow[k];
            if (r >= 0) acc += sw[k] * g_obuf[(size_t)r * HH + h];
        }
        y[(size_t)t * HH + h] = acc;
    }
}

// ====================================================================
extern "C" void kernel_launch(void* const* d_in, const int* in_sizes, int n_in,
                              void* d_out, int out_size)
{
    const float* x        = (const float*)d_in[0];
    const float* w_router = (const float*)d_in[1];
    const float* bias     = (const float*)d_in[2];
    const float* w_gate   = (const float*)d_in[3];
    const float* w_up     = (const float*)d_in[4];
    const float* w_down   = (const float*)d_in[5];

    float* y = (float*)d_out;
    float* logits_out = nullptr;
    float* idx_out    = nullptr;
    long long base = (long long)TT * HH;
    if ((long long)out_size >= base + (long long)TT * EE)
        logits_out = y + base;
    if ((long long)out_size >= base + (long long)TT * EE + (long long)TT * KK)
        idx_out = y + base + (long long)TT * EE;

    router_kernel<<<TT, 256>>>(x, w_router, bias, logits_out, idx_out);
    pos_kernel<<<EE, 256>>>();
    gemm1_mma<<<dim3(CC / 128, FF / 64, EE), 256>>>(x, w_gate, w_up);
    gemm2_mma<<<dim3(CC / 128, HH / 128, EE), 256>>>(w_down);
    combine_kernel<<<TT, 256>>>(y);
}

// round 10
// speedup vs baseline: 4.7043x; 1.0375x over previous
#include <cuda_runtime.h>
#include <cuda_fp16.h>
#include <math.h>
#include <stdint.h>

// Problem constants
#define TT 4096   // tokens = B*S
#define EE 64     // experts
#define KK 8      // top_k
#define HH 1024   // hidden
#define FF 512    // expert ffn
#define CC 1024   // capacity

// -------- scratch (__device__ globals; no allocation allowed) --------
__device__ int   g_expert_index[TT * KK];
__device__ float g_weights[TT * KK];
__device__ int   g_pair_pos[TT * KK];
__device__ int   g_row_token[EE * CC];
__device__ int   g_count[EE];
__device__ alignas(16) __half g_xh[(size_t)TT * HH];         // 8 MB  (x in half)
__device__ alignas(16) __half g_hbuf[(size_t)EE * CC * FF];  // 67 MB (half)
__device__ alignas(16) __half g_obuf[(size_t)EE * CC * HH];  // 134 MB (half)

// -------- helpers --------
__device__ __forceinline__ uint32_t smem_to_u32(const void* p) {
    uint32_t a;
    asm("{ .reg .u64 t; cvta.to.shared.u64 t, %1; cvt.u32.u64 %0, t; }"
        : "=r"(a) : "l"(p));
    return a;
}
__device__ __forceinline__ uint2 f4_to_h4(float4 v) {
    __half2 a = __floats2half2_rn(v.x, v.y);
    __half2 b = __floats2half2_rn(v.z, v.w);
    uint2 r;
    r.x = *reinterpret_cast<uint32_t*>(&a);
    r.y = *reinterpret_cast<uint32_t*>(&b);
    return r;
}
__device__ __forceinline__ void ldm_x4(uint32_t* r, uint32_t addr) {
    asm volatile("ldmatrix.sync.aligned.m8n8.x4.shared.b16 {%0,%1,%2,%3}, [%4];"
        : "=r"(r[0]), "=r"(r[1]), "=r"(r[2]), "=r"(r[3]) : "r"(addr));
}
__device__ __forceinline__ void ldm_x4t(uint32_t* r, uint32_t addr) {
    asm volatile("ldmatrix.sync.aligned.m8n8.x4.trans.shared.b16 {%0,%1,%2,%3}, [%4];"
        : "=r"(r[0]), "=r"(r[1]), "=r"(r[2]), "=r"(r[3]) : "r"(addr));
}
__device__ __forceinline__ void mma_f16(float* c, const uint32_t* a, const uint32_t* b) {
    asm volatile(
        "mma.sync.aligned.m16n8k16.row.col.f32.f16.f16.f32 "
        "{%0,%1,%2,%3},{%4,%5,%6,%7},{%8,%9},{%0,%1,%2,%3};"
        : "+f"(c[0]), "+f"(c[1]), "+f"(c[2]), "+f"(c[3])
        : "r"(a[0]), "r"(a[1]), "r"(a[2]), "r"(a[3]), "r"(b[0]), "r"(b[1]));
}
__device__ __forceinline__ void cp_async16(uint32_t dst, const void* src) {
    asm volatile("cp.async.cg.shared.global [%0], [%1], 16;" :: "r"(dst), "l"(src));
}
#define CP_COMMIT() asm volatile("cp.async.commit_group;" ::: "memory")
#define CP_WAIT0()  asm volatile("cp.async.wait_group 0;" ::: "memory")

// ====================================================================
// Kernel 0: x -> half
// ====================================================================
__global__ void cvt_x_kernel(const float* __restrict__ x)
{
    size_t i = ((size_t)blockIdx.x * 256 + threadIdx.x) * 8;
    float4 v0 = *reinterpret_cast<const float4*>(x + i);
    float4 v1 = *reinterpret_cast<const float4*>(x + i + 4);
    uint2 a = f4_to_h4(v0);
    uint2 b = f4_to_h4(v1);
    uint4 o; o.x = a.x; o.y = a.y; o.z = b.x; o.w = b.y;
    *reinterpret_cast<uint4*>(g_xh + i) = o;
}

// ====================================================================
// Kernel 1: router — exact fp32 (must match reference top-k bitwise)
// ====================================================================
__global__ void router_kernel(const float* __restrict__ x,
                              const float* __restrict__ w_router,
                              const float* __restrict__ bias,
                              float* __restrict__ logits_out,
                              float* __restrict__ idx_out)
{
    int t = blockIdx.x;
    __shared__ alignas(16) float sx[HH];
    __shared__ float slog[EE];
    __shared__ float saff[EE];
    __shared__ float ssel[EE];

    const float* xr = x + (size_t)t * HH;
    for (int i = threadIdx.x; i < HH; i += blockDim.x) sx[i] = xr[i];
    __syncthreads();

    int warp = threadIdx.x >> 5;
    int lane = threadIdx.x & 31;

    for (int e = warp * 8; e < warp * 8 + 8; ++e) {
        const float* wr = w_router + (size_t)e * HH;
        float s = 0.f;
        for (int h = lane; h < HH; h += 32) s += sx[h] * wr[h];
        #pragma unroll
        for (int o = 16; o; o >>= 1) s += __shfl_xor_sync(0xffffffffu, s, o);
        if (lane == 0) {
            slog[e] = s;
            if (logits_out) logits_out[(size_t)t * EE + e] = s;
        }
    }
    __syncthreads();

    if (warp == 0) {
        for (int e = lane; e < EE; e += 32) {
            float l = slog[e];
            float a = 1.0f / (1.0f + expf(-l));
            saff[e] = a;
            ssel[e] = a + bias[e];
        }
        __syncwarp();

        int sel_idx[KK];
        #pragma unroll
        for (int k = 0; k < KK; ++k) {
            float v  = ssel[lane];      int id = lane;
            float v2 = ssel[lane + 32];
            if (v2 > v) { v = v2; id = lane + 32; }
            #pragma unroll
            for (int o = 16; o; o >>= 1) {
                float ov = __shfl_xor_sync(0xffffffffu, v, o);
                int   oi = __shfl_xor_sync(0xffffffffu, id, o);
                if (ov > v || (ov == v && oi < id)) { v = ov; id = oi; }
            }
            sel_idx[k] = id;
            if (lane == 0) ssel[id] = -INFINITY;
            __syncwarp();
        }

        if (lane == 0) {
            float wsum = 0.f;
            float wv[KK];
            #pragma unroll
            for (int k = 0; k < KK; ++k) { wv[k] = saff[sel_idx[k]]; wsum += wv[k]; }
            #pragma unroll
            for (int k = 0; k < KK; ++k) {
                g_expert_index[t * KK + k] = sel_idx[k];
                g_weights[t * KK + k]      = wv[k] / wsum;
                if (idx_out) idx_out[(size_t)t * KK + k] = (float)sel_idx[k];
            }
        }
    }
}

// ====================================================================
// Kernel 2: slot assignment (exact order of flattened [t,k])
// ====================================================================
__global__ void pos_kernel()
{
    int e   = blockIdx.x;
    int tid = threadIdx.x;
    const int NP    = TT * KK;
    const int chunk = NP / 256;
    __shared__ int scnt[256];

    int base = tid * chunk;
    int c = 0;
    for (int j = 0; j < chunk; ++j)
        if (g_expert_index[base + j] == e) c++;
    scnt[tid] = c;
    __syncthreads();

    if (tid == 0) {
        int run = 0;
        for (int i = 0; i < 256; ++i) { int v = scnt[i]; scnt[i] = run; run += v; }
        g_count[e] = run;
    }
    __syncthreads();

    int off = scnt[tid];
    for (int j = 0; j < chunk; ++j) {
        int i = base + j;
        if (g_expert_index[i] == e) {
            g_pair_pos[i] = off;
            if (off < CC) g_row_token[e * CC + off] = i / KK;
            off++;
        }
    }
}

// ====================================================================
// Kernel 3: gate+up GEMM + SiLU*u -> hbuf(half)  (mma.sync fp16 k16)
// CTA: M=128, N=64 (gate+up).  BK=32, double-buffered.
// A via cp.async from g_xh; B fp32->half packed STS.128.
// A tile: [128 rows][32 halves], stride 80B.  B tiles: [32 k][64 n], 144B.
// grid = (CC/128=8 [m fastest], FF/64=8, EE)
// ====================================================================
__global__ void __launch_bounds__(256, 2) gemm1_mma(const float* __restrict__ w_gate,
                                                    const float* __restrict__ w_up)
{
    const int e  = blockIdx.z;
    const int m0 = blockIdx.x * 128;
    const int n0 = blockIdx.y * 64;

    int cnt = g_count[e];
    cnt = (cnt < CC) ? cnt : CC;
    if (m0 >= cnt) return;

    // A0=0(10240) A1=10240, Bg0=20480(4608) Bg1=25088, Bu0=29696 Bu1=34304
    __shared__ alignas(16) unsigned char sbuf[38912];
    __shared__ int stok[128];

    const int tid  = threadIdx.x;
    const int wid  = tid >> 5;
    const int lane = tid & 31;
    const int wm   = wid >> 1;      // 0..3
    const int wn   = wid & 1;       // 0..1

    if (tid < 128) {
        int slot = m0 + tid;
        if (slot >= cnt) slot = cnt - 1;
        stok[tid] = g_row_token[e * CC + slot];
    }
    __syncthreads();

    const uint32_t sA = smem_to_u32(sbuf);

    // ---- loader constants ----
    const int a_row = tid >> 2;                 // 0..63 (+p*64)
    const int a_q4  = tid & 3;                  // 16B chunk within 64B row
    const int b_krow = tid >> 3;                // 0..31
    const int b_n8   = tid & 7;                 // 8 floats each

    const float* wg_base = w_gate + (size_t)e * HH * FF + n0;
    const float* wu_base = w_up   + (size_t)e * HH * FF + n0;
    const __half* xrow0 = g_xh + (size_t)stok[a_row] * HH;
    const __half* xrow1 = g_xh + (size_t)stok[a_row + 64] * HH;

    // ---- fragment address constants ----
    const int fa_row  = (lane & 7) + ((lane >> 3) & 1) * 8;
    const int fa_koff = (lane >> 4) * 16;
    const int fb_k    = (lane & 7) + ((lane >> 3) & 1) * 8;
    const int fb_noff = (wn * 32 + (lane >> 4) * 8) * 2;

    float accg[2][4][4];
    float accu[2][4][4];
    #pragma unroll
    for (int mi = 0; mi < 2; ++mi)
        #pragma unroll
        for (int nj = 0; nj < 4; ++nj)
            #pragma unroll
            for (int qq = 0; qq < 4; ++qq) { accg[mi][nj][qq] = 0.f; accu[mi][nj][qq] = 0.f; }

    float4 bg_pre[2], bu_pre[2];

    // ---- prologue: chunk 0 ----
    {
        const uint32_t Ad = sA + a_row * 80 + a_q4 * 16;
        cp_async16(Ad,            xrow0 + a_q4 * 8);
        cp_async16(Ad + 64 * 80,  xrow1 + a_q4 * 8);
        CP_COMMIT();
        size_t boff = (size_t)b_krow * FF + b_n8 * 8;
        bg_pre[0] = *reinterpret_cast<const float4*>(wg_base + boff);
        bg_pre[1] = *reinterpret_cast<const float4*>(wg_base + boff + 4);
        bu_pre[0] = *reinterpret_cast<const float4*>(wu_base + boff);
        bu_pre[1] = *reinterpret_cast<const float4*>(wu_base + boff + 4);
        int off = b_krow * 144 + b_n8 * 16;
        uint2 lo = f4_to_h4(bg_pre[0]), hi = f4_to_h4(bg_pre[1]);
        *reinterpret_cast<uint4*>(sbuf + 20480 + off) = make_uint4(lo.x, lo.y, hi.x, hi.y);
        lo = f4_to_h4(bu_pre[0]); hi = f4_to_h4(bu_pre[1]);
        *reinterpret_cast<uint4*>(sbuf + 29696 + off) = make_uint4(lo.x, lo.y, hi.x, hi.y);
    }
    CP_WAIT0();
    __syncthreads();

    const int NK = HH / 32;   // 32
    for (int kc = 0; kc < NK; ++kc) {
        const int cur = kc & 1;
        const int has_next = (kc + 1 < NK);
        // issue async A + LDG B for next chunk
        if (has_next) {
            const int k0 = (kc + 1) * 32;
            const uint32_t Ad = sA + (cur ^ 1) * 10240 + a_row * 80 + a_q4 * 16;
            cp_async16(Ad,           xrow0 + k0 + a_q4 * 8);
            cp_async16(Ad + 64 * 80, xrow1 + k0 + a_q4 * 8);
            CP_COMMIT();
            size_t boff = (size_t)(k0 + b_krow) * FF + b_n8 * 8;
            bg_pre[0] = *reinterpret_cast<const float4*>(wg_base + boff);
            bg_pre[1] = *reinterpret_cast<const float4*>(wg_base + boff + 4);
            bu_pre[0] = *reinterpret_cast<const float4*>(wu_base + boff);
            bu_pre[1] = *reinterpret_cast<const float4*>(wu_base + boff + 4);
        }

        // compute current chunk (2 ks of k16)
        const uint32_t Ab  = sA + cur * 10240;
        const uint32_t Bgb = sA + 20480 + cur * 4608;
        const uint32_t Bub = sA + 29696 + cur * 4608;
        #pragma unroll
        for (int ks = 0; ks < 2; ++ks) {
            uint32_t a[2][4];
            #pragma unroll
            for (int mi = 0; mi < 2; ++mi)
                ldm_x4(a[mi], Ab + (wm * 32 + mi * 16 + fa_row) * 80 + ks * 32 + fa_koff);
            #pragma unroll
            for (int pf = 0; pf < 2; ++pf) {
                uint32_t bg[4], bu[4];
                int boff = (ks * 16 + fb_k) * 144 + fb_noff + pf * 32;
                ldm_x4t(bg, Bgb + boff);
                ldm_x4t(bu, Bub + boff);
                #pragma unroll
                for (int mi = 0; mi < 2; ++mi) {
                    mma_f16(accg[mi][pf * 2 + 0], a[mi], bg + 0);
                    mma_f16(accg[mi][pf * 2 + 1], a[mi], bg + 2);
                    mma_f16(accu[mi][pf * 2 + 0], a[mi], bu + 0);
                    mma_f16(accu[mi][pf * 2 + 1], a[mi], bu + 2);
                }
            }
        }

        if (has_next) {
            unsigned char* nbg = sbuf + 20480 + (cur ^ 1) * 4608;
            unsigned char* nbu = sbuf + 29696 + (cur ^ 1) * 4608;
            int off = b_krow * 144 + b_n8 * 16;
            uint2 lo = f4_to_h4(bg_pre[0]), hi = f4_to_h4(bg_pre[1]);
            *reinterpret_cast<uint4*>(nbg + off) = make_uint4(lo.x, lo.y, hi.x, hi.y);
            lo = f4_to_h4(bu_pre[0]); hi = f4_to_h4(bu_pre[1]);
            *reinterpret_cast<uint4*>(nbu + off) = make_uint4(lo.x, lo.y, hi.x, hi.y);
        }
        CP_WAIT0();
        __syncthreads();
    }

    // ---- epilogue: h = silu(g) * u -> half ----
    const int frow = lane >> 2;
    const int fcol = (lane & 3) * 2;
    #pragma unroll
    for (int mi = 0; mi < 2; ++mi) {
        #pragma unroll
        for (int nj = 0; nj < 4; ++nj) {
            int m = m0 + wm * 32 + mi * 16 + frow;
            int n = n0 + wn * 32 + nj * 8 + fcol;
            #pragma unroll
            for (int half = 0; half < 2; ++half) {
                float g0 = accg[mi][nj][half * 2 + 0];
                float g1 = accg[mi][nj][half * 2 + 1];
                float u0 = accu[mi][nj][half * 2 + 0];
                float u1 = accu[mi][nj][half * 2 + 1];
                float h0 = (g0 / (1.0f + expf(-g0))) * u0;
                float h1 = (g1 / (1.0f + expf(-g1))) * u1;
                *reinterpret_cast<__half2*>(
                    &g_hbuf[((size_t)e * CC + m + half * 8) * FF + n]) =
                    __floats2half2_rn(h0, h1);
            }
        }
    }
}

// ====================================================================
// Kernel 4: down GEMM: hbuf(half) x w_down -> obuf(half)
// CTA: M=128, N=128.  BK=32, double-buffered.
// A via cp.async; B fp32->half packed STS.128.
// A tile: [128][32 halves] stride 80B.  B tile: [32 k][128 n] stride 272B.
// grid = (CC/128=8 [m fastest], HH/128=8, EE)
// ====================================================================
__global__ void __launch_bounds__(256, 2) gemm2_mma(const float* __restrict__ w_down)
{
    const int e  = blockIdx.z;
    const int m0 = blockIdx.x * 128;
    const int n0 = blockIdx.y * 128;

    int cnt = g_count[e];
    cnt = (cnt < CC) ? cnt : CC;
    if (m0 >= cnt) return;

    // A0=0(10240) A1=10240, B0=20480(8704) B1=29184; total 37888
    __shared__ alignas(16) unsigned char sbuf[37888];

    const int tid  = threadIdx.x;
    const int wid  = tid >> 5;
    const int lane = tid & 31;
    const int wm   = wid >> 1;
    const int wn   = wid & 1;

    const int a_row = tid >> 2;                 // 0..63 (+p*64)
    const int a_q4  = tid & 3;
    const int b_krow = tid >> 4;                // 0..15 (+p*16)
    const int b_n8   = tid & 15;                // 8 floats

    const __half* a_base = g_hbuf + ((size_t)e * CC + m0) * FF;
    const float*  b_base = w_down + (size_t)e * FF * HH + n0;

    const uint32_t sA = smem_to_u32(sbuf);

    const int fa_row  = (lane & 7) + ((lane >> 3) & 1) * 8;
    const int fa_koff = (lane >> 4) * 16;
    const int fb_k    = (lane & 7) + ((lane >> 3) & 1) * 8;
    const int fb_noff = (wn * 64 + (lane >> 4) * 8) * 2;

    float acc[2][8][4];
    #pragma unroll
    for (int mi = 0; mi < 2; ++mi)
        #pragma unroll
        for (int nj = 0; nj < 8; ++nj)
            #pragma unroll
            for (int qq = 0; qq < 4; ++qq) acc[mi][nj][qq] = 0.f;

    float4 b_pre[4];

    // ---- prologue chunk 0 ----
    {
        const uint32_t Ad = sA + a_row * 80 + a_q4 * 16;
        cp_async16(Ad,           a_base + (size_t)a_row * FF + a_q4 * 8);
        cp_async16(Ad + 64 * 80, a_base + (size_t)(a_row + 64) * FF + a_q4 * 8);
        CP_COMMIT();
        #pragma unroll
        for (int p = 0; p < 2; ++p) {
            size_t boff = (size_t)(b_krow + p * 16) * HH + b_n8 * 8;
            b_pre[p * 2 + 0] = *reinterpret_cast<const float4*>(b_base + boff);
            b_pre[p * 2 + 1] = *reinterpret_cast<const float4*>(b_base + boff + 4);
        }
        #pragma unroll
        for (int p = 0; p < 2; ++p) {
            int off = (b_krow + p * 16) * 272 + b_n8 * 16;
            uint2 lo = f4_to_h4(b_pre[p * 2 + 0]), hi = f4_to_h4(b_pre[p * 2 + 1]);
            *reinterpret_cast<uint4*>(sbuf + 20480 + off) = make_uint4(lo.x, lo.y, hi.x, hi.y);
        }
    }
    CP_WAIT0();
    __syncthreads();

    const int NK = FF / 32;   // 16
    for (int kc = 0; kc < NK; ++kc) {
        const int cur = kc & 1;
        const int has_next = (kc + 1 < NK);
        if (has_next) {
            const int k0 = (kc + 1) * 32;
            const uint32_t Ad = sA + (cur ^ 1) * 10240 + a_row * 80 + a_q4 * 16;
            cp_async16(Ad,           a_base + (size_t)a_row * FF + k0 + a_q4 * 8);
            cp_async16(Ad + 64 * 80, a_base + (size_t)(a_row + 64) * FF + k0 + a_q4 * 8);
            CP_COMMIT();
            #pragma unroll
            for (int p = 0; p < 2; ++p) {
                size_t boff = (size_t)(k0 + b_krow + p * 16) * HH + b_n8 * 8;
                b_pre[p * 2 + 0] = *reinterpret_cast<const float4*>(b_base + boff);
                b_pre[p * 2 + 1] = *reinterpret_cast<const float4*>(b_base + boff + 4);
            }
        }

        const uint32_t Ab = sA + cur * 10240;
        const uint32_t Bb = sA + 20480 + cur * 8704;
        #pragma unroll
        for (int ks = 0; ks < 2; ++ks) {
            uint32_t a[2][4];
            #pragma unroll
            for (int mi = 0; mi < 2; ++mi)
                ldm_x4(a[mi], Ab + (wm * 32 + mi * 16 + fa_row) * 80 + ks * 32 + fa_koff);
            #pragma unroll
            for (int pf = 0; pf < 4; ++pf) {
                uint32_t b[4];
                ldm_x4t(b, Bb + (ks * 16 + fb_k) * 272 + fb_noff + pf * 32);
                #pragma unroll
                for (int mi = 0; mi < 2; ++mi) {
                    mma_f16(acc[mi][pf * 2 + 0], a[mi], b + 0);
                    mma_f16(acc[mi][pf * 2 + 1], a[mi], b + 2);
                }
            }
        }

        if (has_next) {
            unsigned char* nb = sbuf + 20480 + (cur ^ 1) * 8704;
            #pragma unroll
            for (int p = 0; p < 2; ++p) {
                int off = (b_krow + p * 16) * 272 + b_n8 * 16;
                uint2 lo = f4_to_h4(b_pre[p * 2 + 0]), hi = f4_to_h4(b_pre[p * 2 + 1]);
                *reinterpret_cast<uint4*>(nb + off) = make_uint4(lo.x, lo.y, hi.x, hi.y);
            }
        }
        CP_WAIT0();
        __syncthreads();
    }

    const int frow = lane >> 2;
    const int fcol = (lane & 3) * 2;
    #pragma unroll
    for (int mi = 0; mi < 2; ++mi) {
        #pragma unroll
        for (int nj = 0; nj < 8; ++nj) {
            int m = m0 + wm * 32 + mi * 16 + frow;
            int n = n0 + wn * 64 + nj * 8 + fcol;
            #pragma unroll
            for (int half = 0; half < 2; ++half) {
                *reinterpret_cast<__half2*>(
                    &g_obuf[((size_t)e * CC + m + half * 8) * HH + n]) =
                    __floats2half2_rn(acc[mi][nj][half * 2 + 0],
                                      acc[mi][nj][half * 2 + 1]);
            }
        }
    }
}

// ====================================================================
// Kernel 5: combine — y[t] = sum_k w[t,k] * obuf[row(t,k)]  (obuf half)
// ====================================================================
__global__ void combine_kernel(float* __restrict__ y)
{
    int t = blockIdx.x;
    __shared__ int   srow[KK];
    __shared__ float sw[KK];
    if (threadIdx.x < KK) {
        int i = t * KK + threadIdx.x;
        int e = g_expert_index[i];
        int p = g_pair_pos[i];
        srow[threadIdx.x] = (p < CC) ? (e * CC + p) : -1;
        sw[threadIdx.x]   = g_weights[i];
    }
    __syncthreads();

    const int h0 = threadIdx.x * 4;     // 256 threads x 4 = 1024
    float a0 = 0.f, a1 = 0.f, a2 = 0.f, a3 = 0.f;
    #pragma unroll
    for (int k = 0; k < KK; ++k) {
        int r = srow[k];
        if (r >= 0) {
            float wk = sw[k];
            uint2 v = *reinterpret_cast<const uint2*>(&g_obuf[(size_t)r * HH + h0]);
            __half2 p0 = *reinterpret_cast<__half2*>(&v.x);
            __half2 p1 = *reinterpret_cast<__half2*>(&v.y);
            float2 f0 = __half22float2(p0);
            float2 f1 = __half22float2(p1);
            a0 += wk * f0.x; a1 += wk * f0.y;
            a2 += wk * f1.x; a3 += wk * f1.y;
        }
    }
    *reinterpret_cast<float4*>(&y[(size_t)t * HH + h0]) = make_float4(a0, a1, a2, a3);
}

// ====================================================================
extern "C" void kernel_launch(void* const* d_in, const int* in_sizes, int n_in,
                              void* d_out, int out_size)
{
    const float* x        = (const float*)d_in[0];
    const float* w_router = (const float*)d_in[1];
    const float* bias     = (const float*)d_in[2];
    const float* w_gate   = (const float*)d_in[3];
    const float* w_up     = (const float*)d_in[4];
    const float* w_down   = (const float*)d_in[5];

    float* y = (float*)d_out;
    float* logits_out = nullptr;
    float* idx_out    = nullptr;
    long long base = (long long)TT * HH;
    if ((long long)out_size >= base + (long long)TT * EE)
        logits_out = y + base;
    if ((long long)out_size >= base + (long long)TT * EE + (long long)TT * KK)
        idx_out = y + base + (long long)TT * EE;

    cvt_x_kernel<<<(TT * HH) / (256 * 8), 256>>>(x);
    router_kernel<<<TT, 256>>>(x, w_router, bias, logits_out, idx_out);
    pos_kernel<<<EE, 256>>>();
    gemm1_mma<<<dim3(CC / 128, FF / 64, EE), 256>>>(w_gate, w_up);
    gemm2_mma<<<dim3(CC / 128, HH / 128, EE), 256>>>(w_down);
    combine_kernel<<<TT, 256>>>(y);
}